// round 15
// baseline (speedup 1.0000x reference)
#include <cuda_runtime.h>
#include <cuda_fp16.h>
#include <cstdint>
#include <math.h>

#define Bb     32
#define Ss     2048
#define Dd     1280
#define Hh     16
#define HDd    96
#define NLl    64
#define DEPTHn 3
#define FFf    5120
#define SKV    (Ss + NLl)      /* 2112 */
#define HHD    (Hh * HDd)      /* 1536 */
#define EPSf   1e-5f

// ======================= scratch (device globals) ===========================
__device__ float g_lat[Bb * NLl * Dd];
__device__ float g_bias[DEPTHn * 2 * HHD];
__device__ __half g_Qh[Bb * NLl * HHD];
__device__ __half g_K0[(size_t)Bb * SKV * HHD];
__device__ __half g_V0[(size_t)Bb * SKV * HHD];
__device__ __half g_K1[(size_t)Bb * SKV * HHD];
__device__ __half g_V1[(size_t)Bb * SKV * HHD];
__device__ __half g_attnH[Bb * NLl * HHD];
__device__ __half g_Amlp[(size_t)Bb * NLl * FFf];

#define SZ1      1966080u
#define SZFC     6553600u
#define OFF_WQ   0u
#define OFF_WK   (SZ1)
#define OFF_WV   (2u * SZ1)
#define OFF_WKF  (3u * SZ1)
#define OFF_WVF  (4u * SZ1)
#define OFF_WO   (5u * SZ1)
#define OFF_WFC  (6u * SZ1)
#define OFF_WCP  (6u * SZ1 + SZFC)
#define LAYER_W  (6u * SZ1 + 2u * SZFC)
__device__ __half g_W[(size_t)DEPTHn * LAYER_W];
__device__ __half g_Actx[(size_t)Bb * Ss * Dd];
__device__ __half g_Alat[Bb * NLl * Dd];

// ======================= prep kernels ========================================
__global__ void packln_kernel(const float* __restrict__ X,
                              const float* __restrict__ lnw,
                              const float* __restrict__ lnb,
                              __half* __restrict__ out, int ncols) {
    int row = blockIdx.x;
    const float* x = X + (size_t)row * ncols;
    __half* o = out + (size_t)row * ncols;
    float v[8];
    int nv = 0;
    float s = 0.f, ss = 0.f;
    for (int c = threadIdx.x; c < ncols; c += blockDim.x) {
        float t = x[c];
        v[nv++] = t;
        s += t; ss += t * t;
    }
#pragma unroll
    for (int o2 = 16; o2 > 0; o2 >>= 1) {
        s  += __shfl_xor_sync(0xffffffffu, s, o2);
        ss += __shfl_xor_sync(0xffffffffu, ss, o2);
    }
    __shared__ float red_s[8], red_q[8];
    __shared__ float sh_m, sh_r;
    int w = threadIdx.x >> 5, nl = threadIdx.x & 31;
    if (nl == 0) { red_s[w] = s; red_q[w] = ss; }
    __syncthreads();
    if (threadIdx.x == 0) {
        float S = 0.f, Q = 0.f;
        int nw = blockDim.x >> 5;
        for (int i = 0; i < nw; i++) { S += red_s[i]; Q += red_q[i]; }
        float m = S / (float)ncols;
        sh_m = m;
        sh_r = rsqrtf(Q / (float)ncols - m * m + EPSf);
    }
    __syncthreads();
    float mu = sh_m, rs = sh_r;
    nv = 0;
    for (int c = threadIdx.x; c < ncols; c += blockDim.x) {
        float t = (v[nv++] - mu) * rs;
        if (lnw) t = t * lnw[c] + lnb[c];
        o[c] = __float2half_rn(t);
    }
}

__global__ void broadcast_lat_kernel(const float* __restrict__ latents) {
    int i = blockIdx.x * blockDim.x + threadIdx.x;
    const int per = NLl * Dd;
    if (i < Bb * per) g_lat[i] = latents[i % per];
}

__global__ void wt_packh_kernel(const float* __restrict__ W,
                                const float* __restrict__ gamma,
                                __half* __restrict__ out, int K, int N) {
    __shared__ float tile[32][33];
    int n0 = blockIdx.x << 5, k0 = blockIdx.y << 5;
    for (int i = threadIdx.y; i < 32; i += 8)
        tile[i][threadIdx.x] = W[(size_t)(k0 + i) * N + n0 + threadIdx.x];
    __syncthreads();
    float g = gamma ? gamma[k0 + threadIdx.x] : 1.f;
    for (int i = threadIdx.y; i < 32; i += 8)
        out[(size_t)(n0 + i) * K + k0 + threadIdx.x] =
            __float2half_rn(tile[threadIdx.x][i] * g);
}

__global__ void bias_kernel(const float* __restrict__ beta,
                            const float* __restrict__ W,
                            float* __restrict__ out, int K, int N) {
    __shared__ float red[16][17];
    int n = blockIdx.x * 16 + (threadIdx.x & 15);
    int kg = threadIdx.x >> 4;
    float s = 0.f;
    for (int k = kg; k < K; k += 16) s += beta[k] * W[(size_t)k * N + n];
    red[kg][threadIdx.x & 15] = s;
    __syncthreads();
    if (kg == 0) {
        float t = 0.f;
#pragma unroll
        for (int i = 0; i < 16; i++) t += red[i][threadIdx.x & 15];
        out[n] = t;
    }
}

// ===== fp16 HMMA GEMM: template BM (128: 2 CTA/SM | 256: big-tile) =========
#define CP_ASYNC16(dst, src) \
    asm volatile("cp.async.cg.shared.global [%0], [%1], 16;" \
                 :: "r"(dst), "l"(src))
#define CP_COMMIT() asm volatile("cp.async.commit_group;" ::: "memory")
#define CP_WAITG(n) asm volatile("cp.async.wait_group %0;" :: "n"(n) : "memory")

#define LDSM4(r0, r1, r2, r3, addr)                                          \
    asm volatile("ldmatrix.sync.aligned.m8n8.x4.shared.b16 {%0,%1,%2,%3}, [%4];" \
        : "=r"(r0), "=r"(r1), "=r"(r2), "=r"(r3) : "r"(addr))

#define LDSM4T(r0, r1, r2, r3, addr)                                         \
    asm volatile("ldmatrix.sync.aligned.m8n8.x4.trans.shared.b16 {%0,%1,%2,%3}, [%4];" \
        : "=r"(r0), "=r"(r1), "=r"(r2), "=r"(r3) : "r"(addr))

#define MMAH(d, a, b0, b1)                                                   \
    asm volatile("mma.sync.aligned.m16n8k16.row.col.f32.f16.f16.f32 "        \
        "{%0,%1,%2,%3}, {%4,%5,%6,%7}, {%8,%9}, {%0,%1,%2,%3};"              \
        : "+f"((d)[0]), "+f"((d)[1]), "+f"((d)[2]), "+f"((d)[3])             \
        : "r"((a)[0]), "r"((a)[1]), "r"((a)[2]), "r"((a)[3]),                \
          "r"(b0), "r"(b1))

__device__ __forceinline__ uint32_t smem_u32(const void* p) {
    uint32_t a;
    asm("{ .reg .u64 t; cvta.to.shared.u64 t, %1; cvt.u32.u64 %0, t; }"
        : "=r"(a) : "l"(p));
    return a;
}
__device__ __forceinline__ uint32_t swz(uint32_t off) {
    return off ^ ((off >> 3) & 0x70);
}
__device__ __forceinline__ void store2(float* p, float a, float b) {
    *(float2*)p = make_float2(a, b);
}
__device__ __forceinline__ void store2(__half* p, float a, float b) {
    *(__half2*)p = __floats2half2_rn(a, b);
}

#define SMEM128 (3 * (128 * 128 + 16384))   /* 98304  */
#define SMEM256 (3 * (256 * 128 + 16384))   /* 147456 */

// CTA tile BM x 128, warp tile 64x64, warps = (BM/64) x 2, threads = BM.
// split: 0 = single output Cq | 2 = ctx K|V | 3 = latent Q|K|V
template <int BM, typename OutT>
__global__ __launch_bounds__(BM, BM == 128 ? 2 : 1) void gemm_h_kernel(
    const __half* __restrict__ Ain, const __half* __restrict__ Win,
    OutT* __restrict__ Cq, OutT* __restrict__ Ck, OutT* __restrict__ Cv,
    int split, int K, int N, int ldc,
    const float* __restrict__ bias, const float* __restrict__ resid,
    int relu, int remap) {
    constexpr int ABYTES = BM * 128;
    constexpr int ST = ABYTES + 16384;
    constexpr int IB = 1024 / BM;           // 8 (BM=128) or 4 (BM=256)
    constexpr int RSTR = BM / 8;            // copy row stride
    constexpr uint32_t SSTR = (uint32_t)RSTR * 128u;
    extern __shared__ char sm[];
    uint32_t smb = smem_u32(sm);
    int tid = threadIdx.x, wid = tid >> 5, lane = tid & 31;
    int warp_m = wid >> 1, warp_n = wid & 1;

    int m0 = blockIdx.y * BM, n0 = blockIdx.x << 7;
    int NC = K >> 6;

    int rowb = tid >> 3, c16 = tid & 7;
    uint32_t sOf0 = swz((uint32_t)(rowb * 128 + c16 * 16));
    const __half* gA0 = Ain + (size_t)(m0 + rowb) * K + c16 * 8;
    const __half* gB0 = Win + (size_t)(n0 + rowb) * K + c16 * 8;
    size_t KR = (size_t)RSTR * K;

    int lrow = lane & 15, lhalf = lane >> 4;
    int r7 = lrow & 7;
    uint32_t xk[4];
#pragma unroll
    for (int kq = 0; kq < 4; kq++)
        xk[kq] = (uint32_t)(((kq * 2 + lhalf) ^ r7) << 4);
    uint32_t aBase = (uint32_t)((warp_m * 64 + lrow) * 128);
    uint32_t bBase = (uint32_t)ABYTES + (uint32_t)((warp_n * 64 + lrow) * 128);

    float acc[4][8][4];
#pragma unroll
    for (int i = 0; i < 4; i++)
#pragma unroll
        for (int j = 0; j < 8; j++)
#pragma unroll
            for (int k = 0; k < 4; k++) acc[i][j][k] = 0.f;

    auto issue = [&](uint32_t stb, int c) {
        int koff = c * 64;
        const __half* a = gA0 + koff;
        uint32_t so = sOf0;
#pragma unroll
        for (int i = 0; i < 8; i++) {
            CP_ASYNC16(stb + so, a);
            so += SSTR; a += KR;
        }
        const __half* b = gB0 + koff;
        so = sOf0;
#pragma unroll
        for (int i = 0; i < IB; i++) {
            CP_ASYNC16(stb + (uint32_t)ABYTES + so, b);
            so += SSTR; b += KR;
        }
        CP_COMMIT();
    };

    issue(smb, 0);
    issue(smb + (uint32_t)ST, 1);

    for (int c = 0; c < NC; c++) {
        if (c + 1 < NC) { CP_WAITG(1); } else { CP_WAITG(0); }
        __syncthreads();
        uint32_t st = smb + (uint32_t)((c % 3) * ST);
#pragma unroll
        for (int kq = 0; kq < 4; kq++) {
            uint32_t ah[4][4];
#pragma unroll
            for (int mt = 0; mt < 4; mt++)
                LDSM4(ah[mt][0], ah[mt][1], ah[mt][2], ah[mt][3],
                      st + aBase + (uint32_t)(mt * 2048) + xk[kq]);
#pragma unroll
            for (int nt2 = 0; nt2 < 4; nt2++) {
                uint32_t r0, r1, r2, r3;
                LDSM4(r0, r1, r2, r3,
                      st + bBase + (uint32_t)(nt2 * 2048) + xk[kq]);
#pragma unroll
                for (int mt = 0; mt < 4; mt++) {
                    MMAH(acc[mt][nt2 * 2],     ah[mt], r0, r2);
                    MMAH(acc[mt][nt2 * 2 + 1], ah[mt], r1, r3);
                }
            }
        }
        if (c + 2 < NC)
            issue(smb + (uint32_t)(((c + 2) % 3) * ST), c + 2);
    }

    // epilogue: destination by column segment (CTA lies in one segment)
    OutT* Cd = Cq;
    int rm = remap;
    int nloc = n0;
    if (split) {
        int seg = n0 / HHD;
        nloc = n0 - seg * HHD;
        if (split == 2) { Cd = seg ? Cv : Ck; rm = 2; }
        else { Cd = (seg == 0) ? Cq : (seg == 1 ? Ck : Cv); rm = (seg == 0) ? 0 : 1; }
    }
    int qrow = lane >> 2, qcol = (lane & 3) * 2;
#pragma unroll
    for (int mt = 0; mt < 4; mt++) {
#pragma unroll
        for (int half = 0; half < 2; half++) {
            int r = m0 + warp_m * 64 + mt * 16 + half * 8 + qrow;
            int crow;
            if (rm == 1)      crow = (r >> 6)  * SKV + Ss + (r & 63);
            else if (rm == 2) crow = (r >> 11) * SKV + (r & 2047);
            else              crow = r;
            OutT* cp = Cd + (size_t)crow * ldc + nloc + warp_n * 64;
            const float* rp = resid ? resid + (size_t)r * N + n0 + warp_n * 64
                                    : nullptr;
            const float* bp = bias ? bias + n0 + warp_n * 64 : nullptr;
#pragma unroll
            for (int nt = 0; nt < 8; nt++) {
                float v0 = acc[mt][nt][half * 2];
                float v1 = acc[mt][nt][half * 2 + 1];
                int col = nt * 8 + qcol;
                if (bp) { v0 += bp[col]; v1 += bp[col + 1]; }
                if (rp) { v0 += rp[col]; v1 += rp[col + 1]; }
                if (relu) { v0 = fmaxf(v0, 0.f); v1 = fmaxf(v1, 0.f); }
                store2(cp + col, v0, v1);
            }
        }
    }
}

// ======================= HMMA flash attention ===============================
#define AQS   0
#define AKS   13312
#define AVS   26624
#define APS   39936
#define AMB   49152
#define ALR   49664
#define AMX   49920
#define ASM_  50432
#define ATT_SMEM 50944

__global__ __launch_bounds__(256) void attention_kernel(
    const __half* __restrict__ Q, const __half* __restrict__ Kb,
    const __half* __restrict__ Vb, __half* __restrict__ O,
    const float* __restrict__ qw, const float* __restrict__ qb,
    const float* __restrict__ kw, const float* __restrict__ kb) {
    extern __shared__ char smc[];
    __half* qs = (__half*)(smc + AQS);
    __half* ks = (__half*)(smc + AKS);
    __half* vs = (__half*)(smc + AVS);
    __half* psm = (__half*)(smc + APS);
    float* mbuf = (float*)(smc + AMB);
    float* lrun = (float*)(smc + ALR);
    float* rmx  = (float*)(smc + AMX);
    float* rsm  = (float*)(smc + ASM_);
    uint32_t smb = smem_u32(smc);

    int tid = threadIdx.x, wid = tid >> 5, lane = tid & 31;
    int warp_m = wid >> 1, warp_n = wid & 1;
    int b = blockIdx.x >> 4, h = blockIdx.x & 15;
    const float qscale = rsqrtf((float)HDd);

    int jrow = tid >> 2, part = tid & 3;
    int lrow = lane & 15, lhalf = lane >> 4;
    int qrow = lane >> 2, qpair = lane & 3;
    int r0 = warp_m * 16 + qrow, r1 = r0 + 8;

    {
        const __half* qp = Q + (size_t)(b * NLl + jrow) * HHD + h * HDd + part * 24;
        float v[24];
        float s = 0.f, ss = 0.f;
#pragma unroll
        for (int i = 0; i < 3; i++) {
            uint4 t = *(const uint4*)(qp + i * 8);
            __half2* hp = (__half2*)&t;
#pragma unroll
            for (int j = 0; j < 4; j++) {
                float2 f = __half22float2(hp[j]);
                v[i * 8 + 2 * j] = f.x; v[i * 8 + 2 * j + 1] = f.y;
            }
        }
#pragma unroll
        for (int i = 0; i < 24; i++) { s += v[i]; ss += v[i] * v[i]; }
#pragma unroll
        for (int o = 1; o < 4; o <<= 1) {
            s  += __shfl_xor_sync(0xffffffffu, s, o);
            ss += __shfl_xor_sync(0xffffffffu, ss, o);
        }
        float mmu = s * (1.f / 96.f);
        float rsd = rsqrtf(ss * (1.f / 96.f) - mmu * mmu + EPSf);
        __half2 hq[12];
#pragma unroll
        for (int i = 0; i < 12; i++) {
            int c = part * 24 + 2 * i;
            hq[i] = __floats2half2_rn(
                ((v[2 * i]     - mmu) * rsd * qw[c]     + qb[c])     * qscale,
                ((v[2 * i + 1] - mmu) * rsd * qw[c + 1] + qb[c + 1]) * qscale);
        }
        __half* dst = qs + jrow * 104 + part * 24;
        *(uint4*)(dst)      = *(uint4*)&hq[0];
        *(uint4*)(dst + 8)  = *(uint4*)&hq[4];
        *(uint4*)(dst + 16) = *(uint4*)&hq[8];
    }
    if (tid < 64) { mbuf[tid] = -1e30f; lrun[tid] = 0.f; }
    __syncthreads();

    float oac[6][4];
#pragma unroll
    for (int j = 0; j < 6; j++)
#pragma unroll
        for (int k = 0; k < 4; k++) oac[j][k] = 0.f;

    for (int t = 0; t < SKV / 64; t++) {
        {
            int kidx = t * 64 + jrow;
            const __half* kp = Kb + ((size_t)b * SKV + kidx) * HHD + h * HDd + part * 24;
            const __half* vp = Vb + ((size_t)b * SKV + kidx) * HHD + h * HDd + part * 24;
            uint4 kr[3], vr[3];
#pragma unroll
            for (int i = 0; i < 3; i++) {
                kr[i] = *(const uint4*)(kp + i * 8);
                vr[i] = *(const uint4*)(vp + i * 8);
            }
            float kv[24];
#pragma unroll
            for (int i = 0; i < 3; i++) {
                __half2* hk = (__half2*)&kr[i];
#pragma unroll
                for (int j = 0; j < 4; j++) {
                    float2 f = __half22float2(hk[j]);
                    kv[i * 8 + 2 * j] = f.x; kv[i * 8 + 2 * j + 1] = f.y;
                }
            }
            float s = 0.f, ss = 0.f;
#pragma unroll
            for (int i = 0; i < 24; i++) { s += kv[i]; ss += kv[i] * kv[i]; }
#pragma unroll
            for (int o = 1; o < 4; o <<= 1) {
                s  += __shfl_xor_sync(0xffffffffu, s, o);
                ss += __shfl_xor_sync(0xffffffffu, ss, o);
            }
            float mmu = s * (1.f / 96.f);
            float rsd = rsqrtf(ss * (1.f / 96.f) - mmu * mmu + EPSf);
            __half2 hk2[12];
#pragma unroll
            for (int i = 0; i < 12; i++) {
                int c = part * 24 + 2 * i;
                hk2[i] = __floats2half2_rn(
                    (kv[2 * i]     - mmu) * rsd * kw[c]     + kb[c],
                    (kv[2 * i + 1] - mmu) * rsd * kw[c + 1] + kb[c + 1]);
            }
            __half* kd = ks + jrow * 104 + part * 24;
            __half* vd = vs + jrow * 104 + part * 24;
            *(uint4*)(kd)      = *(uint4*)&hk2[0];
            *(uint4*)(kd + 8)  = *(uint4*)&hk2[4];
            *(uint4*)(kd + 16) = *(uint4*)&hk2[8];
            *(uint4*)(vd)      = vr[0];
            *(uint4*)(vd + 8)  = vr[1];
            *(uint4*)(vd + 16) = vr[2];
        }
        __syncthreads();

        float sc[4][4];
#pragma unroll
        for (int i = 0; i < 4; i++)
#pragma unroll
            for (int k = 0; k < 4; k++) sc[i][k] = 0.f;
#pragma unroll
        for (int k6 = 0; k6 < 6; k6++) {
            uint32_t a[4];
            LDSM4(a[0], a[1], a[2], a[3],
                  smb + AQS + (uint32_t)((warp_m * 16 + lrow) * 208 + (k6 * 2 + lhalf) * 16));
#pragma unroll
            for (int nt2 = 0; nt2 < 2; nt2++) {
                uint32_t b0, b1, b2, b3;
                LDSM4(b0, b1, b2, b3,
                      smb + AKS + (uint32_t)((warp_n * 32 + nt2 * 16 + lrow) * 208 +
                                             (k6 * 2 + lhalf) * 16));
                MMAH(sc[nt2 * 2],     a, b0, b2);
                MMAH(sc[nt2 * 2 + 1], a, b1, b3);
            }
        }

        float mx0 = -1e30f, mx1 = -1e30f;
#pragma unroll
        for (int nt = 0; nt < 4; nt++) {
            mx0 = fmaxf(mx0, fmaxf(sc[nt][0], sc[nt][1]));
            mx1 = fmaxf(mx1, fmaxf(sc[nt][2], sc[nt][3]));
        }
        mx0 = fmaxf(mx0, __shfl_xor_sync(0xffffffffu, mx0, 1));
        mx0 = fmaxf(mx0, __shfl_xor_sync(0xffffffffu, mx0, 2));
        mx1 = fmaxf(mx1, __shfl_xor_sync(0xffffffffu, mx1, 1));
        mx1 = fmaxf(mx1, __shfl_xor_sync(0xffffffffu, mx1, 2));
        if (qpair == 0) {
            rmx[r0 * 2 + warp_n] = mx0;
            rmx[r1 * 2 + warp_n] = mx1;
        }
        __syncthreads();

        int p = t & 1;
        float mo0 = mbuf[p * 64 + r0], mo1 = mbuf[p * 64 + r1];
        float mn0 = fmaxf(mo0, fmaxf(rmx[r0 * 2], rmx[r0 * 2 + 1]));
        float mn1 = fmaxf(mo1, fmaxf(rmx[r1 * 2], rmx[r1 * 2 + 1]));
        float cr0 = __expf(mo0 - mn0), cr1 = __expf(mo1 - mn1);
        if (warp_n == 0 && qpair == 0) {
            mbuf[(p ^ 1) * 64 + r0] = mn0;
            mbuf[(p ^ 1) * 64 + r1] = mn1;
        }
        float s0 = 0.f, s1 = 0.f;
#pragma unroll
        for (int nt = 0; nt < 4; nt++) {
            float e0 = __expf(sc[nt][0] - mn0);
            float e1 = __expf(sc[nt][1] - mn0);
            float e2 = __expf(sc[nt][2] - mn1);
            float e3 = __expf(sc[nt][3] - mn1);
            s0 += e0 + e1; s1 += e2 + e3;
            int col = warp_n * 32 + nt * 8 + qpair * 2;
            *(__half2*)(psm + r0 * 72 + col) = __floats2half2_rn(e0, e1);
            *(__half2*)(psm + r1 * 72 + col) = __floats2half2_rn(e2, e3);
        }
        s0 += __shfl_xor_sync(0xffffffffu, s0, 1);
        s0 += __shfl_xor_sync(0xffffffffu, s0, 2);
        s1 += __shfl_xor_sync(0xffffffffu, s1, 1);
        s1 += __shfl_xor_sync(0xffffffffu, s1, 2);
        if (qpair == 0) {
            rsm[r0 * 2 + warp_n] = s0;
            rsm[r1 * 2 + warp_n] = s1;
        }
        __syncthreads();
        if (warp_n == 0 && qpair == 0) {
            lrun[r0] = lrun[r0] * cr0 + rsm[r0 * 2] + rsm[r0 * 2 + 1];
            lrun[r1] = lrun[r1] * cr1 + rsm[r1 * 2] + rsm[r1 * 2 + 1];
        }

#pragma unroll
        for (int j = 0; j < 6; j++) {
            oac[j][0] *= cr0; oac[j][1] *= cr0;
            oac[j][2] *= cr1; oac[j][3] *= cr1;
        }
        int w8 = lane & 7, blk = lane >> 3;
#pragma unroll
        for (int kk = 0; kk < 4; kk++) {
            uint32_t a[4];
            LDSM4(a[0], a[1], a[2], a[3],
                  smb + APS + (uint32_t)((warp_m * 16 + lrow) * 144 + (kk * 2 + lhalf) * 16));
#pragma unroll
            for (int pr = 0; pr < 3; pr++) {
                int vrow = kk * 16 + w8 + 8 * (blk & 1);
                int vcol = warp_n * 48 + pr * 16 + 8 * (blk >> 1);
                uint32_t b0, b1, b2, b3;
                LDSM4T(b0, b1, b2, b3,
                       smb + AVS + (uint32_t)(vrow * 208 + vcol * 2));
                MMAH(oac[pr * 2],     a, b0, b1);
                MMAH(oac[pr * 2 + 1], a, b2, b3);
            }
        }
        __syncthreads();
    }

    float inv0 = 1.f / lrun[r0], inv1 = 1.f / lrun[r1];
#pragma unroll
    for (int j = 0; j < 6; j++) {
        int col = warp_n * 48 + j * 8 + qpair * 2;
        __half* op0 = O + (size_t)(b * NLl + r0) * HHD + h * HDd + col;
        __half* op1 = O + (size_t)(b * NLl + r1) * HHD + h * HDd + col;
        *(__half2*)op0 = __floats2half2_rn(oac[j][0] * inv0, oac[j][1] * inv0);
        *(__half2*)op1 = __floats2half2_rn(oac[j][2] * inv1, oac[j][3] * inv1);
    }
}

// ======================= final layer norm -> d_out ==========================
__global__ void final_ln_kernel(float* __restrict__ out,
                                const float* __restrict__ w,
                                const float* __restrict__ bia) {
    int row = blockIdx.x;
    const float* x = g_lat + (size_t)row * Dd;
    float s = 0.f, ss = 0.f;
    for (int c = threadIdx.x; c < Dd; c += blockDim.x) {
        float v = x[c]; s += v; ss += v * v;
    }
#pragma unroll
    for (int o = 16; o > 0; o >>= 1) {
        s  += __shfl_xor_sync(0xffffffffu, s, o);
        ss += __shfl_xor_sync(0xffffffffu, ss, o);
    }
    __shared__ float red_s[8], red_q[8];
    __shared__ float sh_m, sh_r;
    int wrp = threadIdx.x >> 5, nl = threadIdx.x & 31;
    if (nl == 0) { red_s[wrp] = s; red_q[wrp] = ss; }
    __syncthreads();
    if (threadIdx.x == 0) {
        float S = 0.f, Q = 0.f;
        for (int i = 0; i < 8; i++) { S += red_s[i]; Q += red_q[i]; }
        float m = S / (float)Dd;
        sh_m = m;
        sh_r = rsqrtf(Q / (float)Dd - m * m + EPSf);
    }
    __syncthreads();
    float m = sh_m, r = sh_r;
    for (int c = threadIdx.x; c < Dd; c += blockDim.x)
        out[(size_t)row * Dd + c] = (x[c] - m) * r * w[c] + bia[c];
}

// ======================= launch (dual-stream, record-before-wait) ===========
extern "C" void kernel_launch(void* const* d_in, const int* in_sizes, int n_in,
                              void* d_out, int out_size) {
    const float* context  = (const float*)d_in[0];
    const float* latents  = (const float*)d_in[1];
    const float* ctx_ln_w = (const float*)d_in[2];
    const float* ctx_ln_b = (const float*)d_in[3];
    const float* lat_ln_w = (const float*)d_in[4];
    const float* lat_ln_b = (const float*)d_in[5];
    const float* q_ln_w   = (const float*)d_in[6];
    const float* q_ln_b   = (const float*)d_in[7];
    const float* k_ln_w   = (const float*)d_in[8];
    const float* k_ln_b   = (const float*)d_in[9];
    const float* wq       = (const float*)d_in[10];
    const float* wk       = (const float*)d_in[11];
    const float* wv       = (const float*)d_in[12];
    const float* wo       = (const float*)d_in[13];
    const float* mlp_ln_w = (const float*)d_in[14];
    const float* mlp_ln_b = (const float*)d_in[15];
    const float* w_fc     = (const float*)d_in[16];
    const float* w_cproj  = (const float*)d_in[17];
    const float* fin_w    = (const float*)d_in[18];
    const float* fin_b    = (const float*)d_in[19];
    (void)in_sizes; (void)n_in; (void)out_size;

    float *pLat, *pBias;
    __half *pW, *pActx, *pAlat, *pAmlp, *pQh, *pK0, *pV0, *pK1, *pV1, *pAttnH;
    cudaGetSymbolAddress((void**)&pLat,   g_lat);
    cudaGetSymbolAddress((void**)&pBias,  g_bias);
    cudaGetSymbolAddress((void**)&pW,     g_W);
    cudaGetSymbolAddress((void**)&pActx,  g_Actx);
    cudaGetSymbolAddress((void**)&pAlat,  g_Alat);
    cudaGetSymbolAddress((void**)&pAmlp,  g_Amlp);
    cudaGetSymbolAddress((void**)&pQh,    g_Qh);
    cudaGetSymbolAddress((void**)&pK0,    g_K0);
    cudaGetSymbolAddress((void**)&pV0,    g_V0);
    cudaGetSymbolAddress((void**)&pK1,    g_K1);
    cudaGetSymbolAddress((void**)&pV1,    g_V1);
    cudaGetSymbolAddress((void**)&pAttnH, g_attnH);
    __half* Kb[2] = {pK0, pK1};
    __half* Vb[2] = {pV0, pV1};

    cudaFuncSetAttribute(attention_kernel,
                         cudaFuncAttributeMaxDynamicSharedMemorySize, ATT_SMEM);
    cudaFuncSetAttribute(gemm_h_kernel<128, __half>,
                         cudaFuncAttributeMaxDynamicSharedMemorySize, SMEM128);
    cudaFuncSetAttribute(gemm_h_kernel<128, float>,
                         cudaFuncAttributeMaxDynamicSharedMemorySize, SMEM128);
    cudaFuncSetAttribute(gemm_h_kernel<256, __half>,
                         cudaFuncAttributeMaxDynamicSharedMemorySize, SMEM256);

    cudaStream_t sS;
    cudaStreamCreateWithFlags(&sS, cudaStreamNonBlocking);
    cudaEvent_t evFork, evCtx[DEPTHn], evAttn0;
    cudaEventCreateWithFlags(&evFork, cudaEventDisableTiming);
    cudaEventCreateWithFlags(&evAttn0, cudaEventDisableTiming);
    for (int i = 0; i < DEPTHn; i++)
        cudaEventCreateWithFlags(&evCtx[i], cudaEventDisableTiming);

    const int ML = Bb * NLl;   // 2048
    const int MC = Bb * Ss;    // 65536
    dim3 tb(32, 8);

    auto issue_ctx = [&](int i, int buf) {
        size_t wb = (size_t)i * LAYER_W;
        const float* gci = ctx_ln_w + i * Dd;
        const float* bci = ctx_ln_b + i * Dd;
        wt_packh_kernel<<<dim3(HHD / 32, Dd / 32), tb, 0, sS>>>(
            wk + (size_t)i * Dd * HHD, gci, pW + wb + OFF_WKF, Dd, HHD);
        bias_kernel<<<HHD / 16, 256, 0, sS>>>(
            bci, wk + (size_t)i * Dd * HHD, pBias + (i * 2 + 0) * HHD, Dd, HHD);
        wt_packh_kernel<<<dim3(HHD / 32, Dd / 32), tb, 0, sS>>>(
            wv + (size_t)i * Dd * HHD, gci, pW + wb + OFF_WVF, Dd, HHD);
        bias_kernel<<<HHD / 16, 256, 0, sS>>>(
            bci, wv + (size_t)i * Dd * HHD, pBias + (i * 2 + 1) * HHD, Dd, HHD);
        gemm_h_kernel<256, __half><<<dim3(2 * HHD / 128, MC / 256), 256, SMEM256, sS>>>(
            pActx, pW + wb + OFF_WKF, nullptr, Kb[buf], Vb[buf], 2,
            Dd, 2 * HHD, HHD, pBias + i * 2 * HHD, nullptr, 0, 2);
        cudaEventRecord(evCtx[i], sS);
    };

    packln_kernel<<<MC, 256>>>(context, nullptr, nullptr, pActx, Dd);
    cudaEventRecord(evFork, 0);
    cudaStreamWaitEvent(sS, evFork, 0);

    issue_ctx(0, 0);
    issue_ctx(1, 1);

    for (int i = 0; i < DEPTHn; i++) {
        size_t wb = (size_t)i * LAYER_W;
        wt_packh_kernel<<<dim3(HHD / 32, Dd / 32), tb>>>(
            wq + (size_t)i * Dd * HHD, nullptr, pW + wb + OFF_WQ, Dd, HHD);
        wt_packh_kernel<<<dim3(HHD / 32, Dd / 32), tb>>>(
            wk + (size_t)i * Dd * HHD, nullptr, pW + wb + OFF_WK, Dd, HHD);
        wt_packh_kernel<<<dim3(HHD / 32, Dd / 32), tb>>>(
            wv + (size_t)i * Dd * HHD, nullptr, pW + wb + OFF_WV, Dd, HHD);
        wt_packh_kernel<<<dim3(Dd / 32, HHD / 32), tb>>>(
            wo + (size_t)i * HHD * Dd, nullptr, pW + wb + OFF_WO, HHD, Dd);
        wt_packh_kernel<<<dim3(FFf / 32, Dd / 32), tb>>>(
            w_fc + (size_t)i * Dd * FFf, nullptr, pW + wb + OFF_WFC, Dd, FFf);
        wt_packh_kernel<<<dim3(Dd / 32, FFf / 32), tb>>>(
            w_cproj + (size_t)i * FFf * Dd, nullptr, pW + wb + OFF_WCP, FFf, Dd);
    }
    broadcast_lat_kernel<<<(Bb * NLl * Dd + 255) / 256, 256>>>(latents);

    for (int i = 0; i < DEPTHn; i++) {
        size_t wb = (size_t)i * LAYER_W;
        const float* llw = lat_ln_w + i * Dd, *llb = lat_ln_b + i * Dd;
        const float* mlw = mlp_ln_w + i * Dd, *mlb = mlp_ln_b + i * Dd;
        const float* qlw = q_ln_w + i * HDd, *qlb = q_ln_b + i * HDd;
        const float* klw = k_ln_w + i * HDd, *klb = k_ln_b + i * HDd;
        int buf = i & 1;

        packln_kernel<<<ML, 256>>>(pLat, llw, llb, pAlat, Dd);
        gemm_h_kernel<128, __half><<<dim3(3 * HHD / 128, ML / 128), 128, SMEM128>>>(
            pAlat, pW + wb + OFF_WQ, pQh, Kb[buf], Vb[buf], 3,
            Dd, 3 * HHD, HHD, nullptr, nullptr, 0, 0);

        cudaStreamWaitEvent(0, evCtx[i], 0);
        attention_kernel<<<Bb * Hh, 256, ATT_SMEM>>>(pQh, Kb[buf], Vb[buf],
                                                     pAttnH, qlw, qlb, klw, klb);
        if (i == 0) {
            cudaEventRecord(evAttn0, 0);
            cudaStreamWaitEvent(sS, evAttn0, 0);
            issue_ctx(2, 0);
        }

        gemm_h_kernel<128, float><<<dim3(Dd / 128, ML / 128), 128, SMEM128>>>(
            pAttnH, pW + wb + OFF_WO, pLat, nullptr, nullptr, 0,
            HHD, Dd, Dd, nullptr, pLat, 0, 0);

        packln_kernel<<<ML, 256>>>(pLat, mlw, mlb, pAlat, Dd);
        gemm_h_kernel<128, __half><<<dim3(FFf / 128, ML / 128), 128, SMEM128>>>(
            pAlat, pW + wb + OFF_WFC, pAmlp, nullptr, nullptr, 0,
            Dd, FFf, FFf, nullptr, nullptr, 1, 0);
        gemm_h_kernel<128, float><<<dim3(Dd / 128, ML / 128), 128, SMEM128>>>(
            pAmlp, pW + wb + OFF_WCP, pLat, nullptr, nullptr, 0,
            FFf, Dd, Dd, nullptr, pLat, 0, 0);
    }

    final_ln_kernel<<<Bb * NLl, 256>>>((float*)d_out, fin_w, fin_b);
}

// round 16
// speedup vs baseline: 1.0376x; 1.0376x over previous
#include <cuda_runtime.h>
#include <cuda_fp16.h>
#include <cstdint>
#include <math.h>

#define Bb     32
#define Ss     2048
#define Dd     1280
#define Hh     16
#define HDd    96
#define NLl    64
#define DEPTHn 3
#define FFf    5120
#define SKV    (Ss + NLl)      /* 2112 */
#define HHD    (Hh * HDd)      /* 1536 */
#define EPSf   1e-5f

// ======================= scratch (device globals) ===========================
__device__ float g_lat[Bb * NLl * Dd];
__device__ float g_bias[DEPTHn * 2 * HHD];
__device__ __half g_Qh[Bb * NLl * HHD];
__device__ __half g_K0[(size_t)Bb * SKV * HHD];
__device__ __half g_V0[(size_t)Bb * SKV * HHD];
__device__ __half g_K1[(size_t)Bb * SKV * HHD];
__device__ __half g_V1[(size_t)Bb * SKV * HHD];
__device__ __half g_attnH[Bb * NLl * HHD];
__device__ __half g_Amlp[(size_t)Bb * NLl * FFf];

#define SZ1      1966080u
#define SZFC     6553600u
#define OFF_WQ   0u
#define OFF_WK   (SZ1)
#define OFF_WV   (2u * SZ1)
#define OFF_WKF  (3u * SZ1)
#define OFF_WVF  (4u * SZ1)
#define OFF_WO   (5u * SZ1)
#define OFF_WFC  (6u * SZ1)
#define OFF_WCP  (6u * SZ1 + SZFC)
#define LAYER_W  (6u * SZ1 + 2u * SZFC)
__device__ __half g_W[(size_t)DEPTHn * LAYER_W];
__device__ __half g_Actx[(size_t)Bb * Ss * Dd];
__device__ __half g_Alat[Bb * NLl * Dd];

// ======================= prep kernels ========================================
__global__ void packln_kernel(const float* __restrict__ X,
                              const float* __restrict__ lnw,
                              const float* __restrict__ lnb,
                              __half* __restrict__ out, int ncols) {
    int row = blockIdx.x;
    const float* x = X + (size_t)row * ncols;
    __half* o = out + (size_t)row * ncols;
    float v[8];
    int nv = 0;
    float s = 0.f, ss = 0.f;
    for (int c = threadIdx.x; c < ncols; c += blockDim.x) {
        float t = x[c];
        v[nv++] = t;
        s += t; ss += t * t;
    }
#pragma unroll
    for (int o2 = 16; o2 > 0; o2 >>= 1) {
        s  += __shfl_xor_sync(0xffffffffu, s, o2);
        ss += __shfl_xor_sync(0xffffffffu, ss, o2);
    }
    __shared__ float red_s[8], red_q[8];
    __shared__ float sh_m, sh_r;
    int w = threadIdx.x >> 5, nl = threadIdx.x & 31;
    if (nl == 0) { red_s[w] = s; red_q[w] = ss; }
    __syncthreads();
    if (threadIdx.x == 0) {
        float S = 0.f, Q = 0.f;
        int nw = blockDim.x >> 5;
        for (int i = 0; i < nw; i++) { S += red_s[i]; Q += red_q[i]; }
        float m = S / (float)ncols;
        sh_m = m;
        sh_r = rsqrtf(Q / (float)ncols - m * m + EPSf);
    }
    __syncthreads();
    float mu = sh_m, rs = sh_r;
    nv = 0;
    for (int c = threadIdx.x; c < ncols; c += blockDim.x) {
        float t = (v[nv++] - mu) * rs;
        if (lnw) t = t * lnw[c] + lnb[c];
        o[c] = __float2half_rn(t);
    }
}

__global__ void broadcast_lat_kernel(const float* __restrict__ latents) {
    int i = blockIdx.x * blockDim.x + threadIdx.x;
    const int per = NLl * Dd;
    if (i < Bb * per) g_lat[i] = latents[i % per];
}

__global__ void wt_packh_kernel(const float* __restrict__ W,
                                const float* __restrict__ gamma,
                                __half* __restrict__ out, int K, int N) {
    __shared__ float tile[32][33];
    int n0 = blockIdx.x << 5, k0 = blockIdx.y << 5;
    for (int i = threadIdx.y; i < 32; i += 8)
        tile[i][threadIdx.x] = W[(size_t)(k0 + i) * N + n0 + threadIdx.x];
    __syncthreads();
    float g = gamma ? gamma[k0 + threadIdx.x] : 1.f;
    for (int i = threadIdx.y; i < 32; i += 8)
        out[(size_t)(n0 + i) * K + k0 + threadIdx.x] =
            __float2half_rn(tile[threadIdx.x][i] * g);
}

// batched transpose-pack: z selects among 3 (W, out) pairs, no gamma
__global__ void wt_packh3_kernel(const float* __restrict__ W0,
                                 const float* __restrict__ W1,
                                 const float* __restrict__ W2,
                                 __half* __restrict__ o0,
                                 __half* __restrict__ o1,
                                 __half* __restrict__ o2, int K, int N) {
    const float* W = (blockIdx.z == 0) ? W0 : (blockIdx.z == 1 ? W1 : W2);
    __half* out    = (blockIdx.z == 0) ? o0 : (blockIdx.z == 1 ? o1 : o2);
    __shared__ float tile[32][33];
    int n0 = blockIdx.x << 5, k0 = blockIdx.y << 5;
    for (int i = threadIdx.y; i < 32; i += 8)
        tile[i][threadIdx.x] = W[(size_t)(k0 + i) * N + n0 + threadIdx.x];
    __syncthreads();
    for (int i = threadIdx.y; i < 32; i += 8)
        out[(size_t)(n0 + i) * K + k0 + threadIdx.x] =
            __float2half_rn(tile[threadIdx.x][i]);
}

__global__ void bias_kernel(const float* __restrict__ beta,
                            const float* __restrict__ W,
                            float* __restrict__ out, int K, int N) {
    __shared__ float red[16][17];
    int n = blockIdx.x * 16 + (threadIdx.x & 15);
    int kg = threadIdx.x >> 4;
    float s = 0.f;
    for (int k = kg; k < K; k += 16) s += beta[k] * W[(size_t)k * N + n];
    red[kg][threadIdx.x & 15] = s;
    __syncthreads();
    if (kg == 0) {
        float t = 0.f;
#pragma unroll
        for (int i = 0; i < 16; i++) t += red[i][threadIdx.x & 15];
        out[n] = t;
    }
}

// ===== fp16 HMMA GEMM: CTA 128x128, 4 warps (64x64 tiles), 2 CTA/SM ========
#define CP_ASYNC16(dst, src) \
    asm volatile("cp.async.cg.shared.global [%0], [%1], 16;" \
                 :: "r"(dst), "l"(src))
#define CP_COMMIT() asm volatile("cp.async.commit_group;" ::: "memory")
#define CP_WAITG(n) asm volatile("cp.async.wait_group %0;" :: "n"(n) : "memory")

#define LDSM4(r0, r1, r2, r3, addr)                                          \
    asm volatile("ldmatrix.sync.aligned.m8n8.x4.shared.b16 {%0,%1,%2,%3}, [%4];" \
        : "=r"(r0), "=r"(r1), "=r"(r2), "=r"(r3) : "r"(addr))

#define LDSM4T(r0, r1, r2, r3, addr)                                         \
    asm volatile("ldmatrix.sync.aligned.m8n8.x4.trans.shared.b16 {%0,%1,%2,%3}, [%4];" \
        : "=r"(r0), "=r"(r1), "=r"(r2), "=r"(r3) : "r"(addr))

#define MMAH(d, a, b0, b1)                                                   \
    asm volatile("mma.sync.aligned.m16n8k16.row.col.f32.f16.f16.f32 "        \
        "{%0,%1,%2,%3}, {%4,%5,%6,%7}, {%8,%9}, {%0,%1,%2,%3};"              \
        : "+f"((d)[0]), "+f"((d)[1]), "+f"((d)[2]), "+f"((d)[3])             \
        : "r"((a)[0]), "r"((a)[1]), "r"((a)[2]), "r"((a)[3]),                \
          "r"(b0), "r"(b1))

__device__ __forceinline__ uint32_t smem_u32(const void* p) {
    uint32_t a;
    asm("{ .reg .u64 t; cvta.to.shared.u64 t, %1; cvt.u32.u64 %0, t; }"
        : "=r"(a) : "l"(p));
    return a;
}
__device__ __forceinline__ uint32_t swz(uint32_t off) {
    return off ^ ((off >> 3) & 0x70);
}
__device__ __forceinline__ void store2(float* p, float a, float b) {
    *(float2*)p = make_float2(a, b);
}
__device__ __forceinline__ void store2(__half* p, float a, float b) {
    *(__half2*)p = __floats2half2_rn(a, b);
}

#define GST    32768
#define GSMEM  (3 * GST)   /* 98304 -> 2 CTAs/SM */

// split: 0 = single output Cq | 2 = ctx K|V | 3 = latent Q|K|V
template <typename OutT>
__global__ __launch_bounds__(128, 2) void gemm_h_kernel(
    const __half* __restrict__ Ain, const __half* __restrict__ Win,
    OutT* __restrict__ Cq, OutT* __restrict__ Ck, OutT* __restrict__ Cv,
    int split, int K, int N, int ldc,
    const float* __restrict__ bias, const float* __restrict__ resid,
    int relu, int remap) {
    extern __shared__ char sm[];
    uint32_t smb = smem_u32(sm);
    int tid = threadIdx.x, wid = tid >> 5, lane = tid & 31;
    int warp_m = wid >> 1, warp_n = wid & 1;

    int m0 = blockIdx.y << 7, n0 = blockIdx.x << 7;
    int NC = K >> 6;

    int rowb = tid >> 3, c16 = tid & 7;
    uint32_t sOf0 = swz((uint32_t)(rowb * 128 + c16 * 16));
    const __half* gA0 = Ain + (size_t)(m0 + rowb) * K + c16 * 8;
    const __half* gB0 = Win + (size_t)(n0 + rowb) * K + c16 * 8;
    size_t K16 = (size_t)16 * K;

    int lrow = lane & 15, lhalf = lane >> 4;
    int r7 = lrow & 7;
    uint32_t xk[4];
#pragma unroll
    for (int kq = 0; kq < 4; kq++)
        xk[kq] = (uint32_t)(((kq * 2 + lhalf) ^ r7) << 4);
    uint32_t aBase = (uint32_t)((warp_m * 64 + lrow) * 128);
    uint32_t bBase = 16384u + (uint32_t)((warp_n * 64 + lrow) * 128);

    float acc[4][8][4];
#pragma unroll
    for (int i = 0; i < 4; i++)
#pragma unroll
        for (int j = 0; j < 8; j++)
#pragma unroll
            for (int k = 0; k < 4; k++) acc[i][j][k] = 0.f;

#pragma unroll
    for (int pc = 0; pc < 2; pc++) {
        uint32_t stb = smb + (uint32_t)(pc * GST);
        int koff = pc * 64;
        const __half* a = gA0 + koff;
        const __half* b = gB0 + koff;
        uint32_t so = sOf0;
#pragma unroll
        for (int i = 0; i < 8; i++) {
            CP_ASYNC16(stb + so, a);
            CP_ASYNC16(stb + 16384u + so, b);
            so += 2048u; a += K16; b += K16;
        }
        CP_COMMIT();
    }

    for (int c = 0; c < NC; c++) {
        if (c + 1 < NC) { CP_WAITG(1); } else { CP_WAITG(0); }
        __syncthreads();
        uint32_t st = smb + (uint32_t)((c % 3) * GST);
#pragma unroll
        for (int kq = 0; kq < 4; kq++) {
            uint32_t ah[4][4];
#pragma unroll
            for (int mt = 0; mt < 4; mt++)
                LDSM4(ah[mt][0], ah[mt][1], ah[mt][2], ah[mt][3],
                      st + aBase + (uint32_t)(mt * 2048) + xk[kq]);
#pragma unroll
            for (int nt2 = 0; nt2 < 4; nt2++) {
                uint32_t r0, r1, r2, r3;
                LDSM4(r0, r1, r2, r3,
                      st + bBase + (uint32_t)(nt2 * 2048) + xk[kq]);
#pragma unroll
                for (int mt = 0; mt < 4; mt++) {
                    MMAH(acc[mt][nt2 * 2],     ah[mt], r0, r2);
                    MMAH(acc[mt][nt2 * 2 + 1], ah[mt], r1, r3);
                }
            }
        }
        if (c + 2 < NC) {
            uint32_t stb = smb + (uint32_t)(((c + 2) % 3) * GST);
            int koff = (c + 2) * 64;
            const __half* a = gA0 + koff;
            const __half* b = gB0 + koff;
            uint32_t so = sOf0;
#pragma unroll
            for (int i = 0; i < 8; i++) {
                CP_ASYNC16(stb + so, a);
                CP_ASYNC16(stb + 16384u + so, b);
                so += 2048u; a += K16; b += K16;
            }
            CP_COMMIT();
        }
    }

    // epilogue: destination by column segment (CTA lies in one segment)
    OutT* Cd = Cq;
    int rm = remap;
    int nloc = n0;
    if (split) {
        int seg = n0 / HHD;
        nloc = n0 - seg * HHD;
        if (split == 2) { Cd = seg ? Cv : Ck; rm = 2; }
        else { Cd = (seg == 0) ? Cq : (seg == 1 ? Ck : Cv); rm = (seg == 0) ? 0 : 1; }
    }
    int qrow = lane >> 2, qcol = (lane & 3) * 2;
#pragma unroll
    for (int mt = 0; mt < 4; mt++) {
#pragma unroll
        for (int half = 0; half < 2; half++) {
            int r = m0 + warp_m * 64 + mt * 16 + half * 8 + qrow;
            int crow;
            if (rm == 1)      crow = (r >> 6)  * SKV + Ss + (r & 63);
            else if (rm == 2) crow = (r >> 11) * SKV + (r & 2047);
            else              crow = r;
            OutT* cp = Cd + (size_t)crow * ldc + nloc + warp_n * 64;
            const float* rp = resid ? resid + (size_t)r * N + n0 + warp_n * 64
                                    : nullptr;
            const float* bp = bias ? bias + n0 + warp_n * 64 : nullptr;
#pragma unroll
            for (int nt = 0; nt < 8; nt++) {
                float v0 = acc[mt][nt][half * 2];
                float v1 = acc[mt][nt][half * 2 + 1];
                int col = nt * 8 + qcol;
                if (bp) { v0 += bp[col]; v1 += bp[col + 1]; }
                if (rp) { v0 += rp[col]; v1 += rp[col + 1]; }
                if (relu) { v0 = fmaxf(v0, 0.f); v1 = fmaxf(v1, 0.f); }
                store2(cp + col, v0, v1);
            }
        }
    }
}

// ======================= HMMA flash attention ===============================
#define AQS   0
#define AKS   13312
#define AVS   26624
#define APS   39936
#define AMB   49152
#define ALR   49664
#define AMX   49920
#define ASM_  50432
#define ATT_SMEM 50944

__global__ __launch_bounds__(256) void attention_kernel(
    const __half* __restrict__ Q, const __half* __restrict__ Kb,
    const __half* __restrict__ Vb, __half* __restrict__ O,
    const float* __restrict__ qw, const float* __restrict__ qb,
    const float* __restrict__ kw, const float* __restrict__ kb) {
    extern __shared__ char smc[];
    __half* qs = (__half*)(smc + AQS);
    __half* ks = (__half*)(smc + AKS);
    __half* vs = (__half*)(smc + AVS);
    __half* psm = (__half*)(smc + APS);
    float* mbuf = (float*)(smc + AMB);
    float* lrun = (float*)(smc + ALR);
    float* rmx  = (float*)(smc + AMX);
    float* rsm  = (float*)(smc + ASM_);
    uint32_t smb = smem_u32(smc);

    int tid = threadIdx.x, wid = tid >> 5, lane = tid & 31;
    int warp_m = wid >> 1, warp_n = wid & 1;
    int b = blockIdx.x >> 4, h = blockIdx.x & 15;
    const float qscale = rsqrtf((float)HDd);

    int jrow = tid >> 2, part = tid & 3;
    int lrow = lane & 15, lhalf = lane >> 4;
    int qrow = lane >> 2, qpair = lane & 3;
    int r0 = warp_m * 16 + qrow, r1 = r0 + 8;

    {
        const __half* qp = Q + (size_t)(b * NLl + jrow) * HHD + h * HDd + part * 24;
        float v[24];
        float s = 0.f, ss = 0.f;
#pragma unroll
        for (int i = 0; i < 3; i++) {
            uint4 t = *(const uint4*)(qp + i * 8);
            __half2* hp = (__half2*)&t;
#pragma unroll
            for (int j = 0; j < 4; j++) {
                float2 f = __half22float2(hp[j]);
                v[i * 8 + 2 * j] = f.x; v[i * 8 + 2 * j + 1] = f.y;
            }
        }
#pragma unroll
        for (int i = 0; i < 24; i++) { s += v[i]; ss += v[i] * v[i]; }
#pragma unroll
        for (int o = 1; o < 4; o <<= 1) {
            s  += __shfl_xor_sync(0xffffffffu, s, o);
            ss += __shfl_xor_sync(0xffffffffu, ss, o);
        }
        float mmu = s * (1.f / 96.f);
        float rsd = rsqrtf(ss * (1.f / 96.f) - mmu * mmu + EPSf);
        __half2 hq[12];
#pragma unroll
        for (int i = 0; i < 12; i++) {
            int c = part * 24 + 2 * i;
            hq[i] = __floats2half2_rn(
                ((v[2 * i]     - mmu) * rsd * qw[c]     + qb[c])     * qscale,
                ((v[2 * i + 1] - mmu) * rsd * qw[c + 1] + qb[c + 1]) * qscale);
        }
        __half* dst = qs + jrow * 104 + part * 24;
        *(uint4*)(dst)      = *(uint4*)&hq[0];
        *(uint4*)(dst + 8)  = *(uint4*)&hq[4];
        *(uint4*)(dst + 16) = *(uint4*)&hq[8];
    }
    if (tid < 64) { mbuf[tid] = -1e30f; lrun[tid] = 0.f; }
    __syncthreads();

    float oac[6][4];
#pragma unroll
    for (int j = 0; j < 6; j++)
#pragma unroll
        for (int k = 0; k < 4; k++) oac[j][k] = 0.f;

    for (int t = 0; t < SKV / 64; t++) {
        {
            int kidx = t * 64 + jrow;
            const __half* kp = Kb + ((size_t)b * SKV + kidx) * HHD + h * HDd + part * 24;
            const __half* vp = Vb + ((size_t)b * SKV + kidx) * HHD + h * HDd + part * 24;
            uint4 kr[3], vr[3];
#pragma unroll
            for (int i = 0; i < 3; i++) {
                kr[i] = *(const uint4*)(kp + i * 8);
                vr[i] = *(const uint4*)(vp + i * 8);
            }
            float kv[24];
#pragma unroll
            for (int i = 0; i < 3; i++) {
                __half2* hk = (__half2*)&kr[i];
#pragma unroll
                for (int j = 0; j < 4; j++) {
                    float2 f = __half22float2(hk[j]);
                    kv[i * 8 + 2 * j] = f.x; kv[i * 8 + 2 * j + 1] = f.y;
                }
            }
            float s = 0.f, ss = 0.f;
#pragma unroll
            for (int i = 0; i < 24; i++) { s += kv[i]; ss += kv[i] * kv[i]; }
#pragma unroll
            for (int o = 1; o < 4; o <<= 1) {
                s  += __shfl_xor_sync(0xffffffffu, s, o);
                ss += __shfl_xor_sync(0xffffffffu, ss, o);
            }
            float mmu = s * (1.f / 96.f);
            float rsd = rsqrtf(ss * (1.f / 96.f) - mmu * mmu + EPSf);
            __half2 hk2[12];
#pragma unroll
            for (int i = 0; i < 12; i++) {
                int c = part * 24 + 2 * i;
                hk2[i] = __floats2half2_rn(
                    (kv[2 * i]     - mmu) * rsd * kw[c]     + kb[c],
                    (kv[2 * i + 1] - mmu) * rsd * kw[c + 1] + kb[c + 1]);
            }
            __half* kd = ks + jrow * 104 + part * 24;
            __half* vd = vs + jrow * 104 + part * 24;
            *(uint4*)(kd)      = *(uint4*)&hk2[0];
            *(uint4*)(kd + 8)  = *(uint4*)&hk2[4];
            *(uint4*)(kd + 16) = *(uint4*)&hk2[8];
            *(uint4*)(vd)      = vr[0];
            *(uint4*)(vd + 8)  = vr[1];
            *(uint4*)(vd + 16) = vr[2];
        }
        __syncthreads();

        float sc[4][4];
#pragma unroll
        for (int i = 0; i < 4; i++)
#pragma unroll
            for (int k = 0; k < 4; k++) sc[i][k] = 0.f;
#pragma unroll
        for (int k6 = 0; k6 < 6; k6++) {
            uint32_t a[4];
            LDSM4(a[0], a[1], a[2], a[3],
                  smb + AQS + (uint32_t)((warp_m * 16 + lrow) * 208 + (k6 * 2 + lhalf) * 16));
#pragma unroll
            for (int nt2 = 0; nt2 < 2; nt2++) {
                uint32_t b0, b1, b2, b3;
                LDSM4(b0, b1, b2, b3,
                      smb + AKS + (uint32_t)((warp_n * 32 + nt2 * 16 + lrow) * 208 +
                                             (k6 * 2 + lhalf) * 16));
                MMAH(sc[nt2 * 2],     a, b0, b2);
                MMAH(sc[nt2 * 2 + 1], a, b1, b3);
            }
        }

        float mx0 = -1e30f, mx1 = -1e30f;
#pragma unroll
        for (int nt = 0; nt < 4; nt++) {
            mx0 = fmaxf(mx0, fmaxf(sc[nt][0], sc[nt][1]));
            mx1 = fmaxf(mx1, fmaxf(sc[nt][2], sc[nt][3]));
        }
        mx0 = fmaxf(mx0, __shfl_xor_sync(0xffffffffu, mx0, 1));
        mx0 = fmaxf(mx0, __shfl_xor_sync(0xffffffffu, mx0, 2));
        mx1 = fmaxf(mx1, __shfl_xor_sync(0xffffffffu, mx1, 1));
        mx1 = fmaxf(mx1, __shfl_xor_sync(0xffffffffu, mx1, 2));
        if (qpair == 0) {
            rmx[r0 * 2 + warp_n] = mx0;
            rmx[r1 * 2 + warp_n] = mx1;
        }
        __syncthreads();

        int p = t & 1;
        float mo0 = mbuf[p * 64 + r0], mo1 = mbuf[p * 64 + r1];
        float mn0 = fmaxf(mo0, fmaxf(rmx[r0 * 2], rmx[r0 * 2 + 1]));
        float mn1 = fmaxf(mo1, fmaxf(rmx[r1 * 2], rmx[r1 * 2 + 1]));
        float cr0 = __expf(mo0 - mn0), cr1 = __expf(mo1 - mn1);
        if (warp_n == 0 && qpair == 0) {
            mbuf[(p ^ 1) * 64 + r0] = mn0;
            mbuf[(p ^ 1) * 64 + r1] = mn1;
        }
        float s0 = 0.f, s1 = 0.f;
#pragma unroll
        for (int nt = 0; nt < 4; nt++) {
            float e0 = __expf(sc[nt][0] - mn0);
            float e1 = __expf(sc[nt][1] - mn0);
            float e2 = __expf(sc[nt][2] - mn1);
            float e3 = __expf(sc[nt][3] - mn1);
            s0 += e0 + e1; s1 += e2 + e3;
            int col = warp_n * 32 + nt * 8 + qpair * 2;
            *(__half2*)(psm + r0 * 72 + col) = __floats2half2_rn(e0, e1);
            *(__half2*)(psm + r1 * 72 + col) = __floats2half2_rn(e2, e3);
        }
        s0 += __shfl_xor_sync(0xffffffffu, s0, 1);
        s0 += __shfl_xor_sync(0xffffffffu, s0, 2);
        s1 += __shfl_xor_sync(0xffffffffu, s1, 1);
        s1 += __shfl_xor_sync(0xffffffffu, s1, 2);
        if (qpair == 0) {
            rsm[r0 * 2 + warp_n] = s0;
            rsm[r1 * 2 + warp_n] = s1;
        }
        __syncthreads();
        if (warp_n == 0 && qpair == 0) {
            lrun[r0] = lrun[r0] * cr0 + rsm[r0 * 2] + rsm[r0 * 2 + 1];
            lrun[r1] = lrun[r1] * cr1 + rsm[r1 * 2] + rsm[r1 * 2 + 1];
        }

#pragma unroll
        for (int j = 0; j < 6; j++) {
            oac[j][0] *= cr0; oac[j][1] *= cr0;
            oac[j][2] *= cr1; oac[j][3] *= cr1;
        }
        int w8 = lane & 7, blk = lane >> 3;
#pragma unroll
        for (int kk = 0; kk < 4; kk++) {
            uint32_t a[4];
            LDSM4(a[0], a[1], a[2], a[3],
                  smb + APS + (uint32_t)((warp_m * 16 + lrow) * 144 + (kk * 2 + lhalf) * 16));
#pragma unroll
            for (int pr = 0; pr < 3; pr++) {
                int vrow = kk * 16 + w8 + 8 * (blk & 1);
                int vcol = warp_n * 48 + pr * 16 + 8 * (blk >> 1);
                uint32_t b0, b1, b2, b3;
                LDSM4T(b0, b1, b2, b3,
                       smb + AVS + (uint32_t)(vrow * 208 + vcol * 2));
                MMAH(oac[pr * 2],     a, b0, b1);
                MMAH(oac[pr * 2 + 1], a, b2, b3);
            }
        }
        __syncthreads();
    }

    float inv0 = 1.f / lrun[r0], inv1 = 1.f / lrun[r1];
#pragma unroll
    for (int j = 0; j < 6; j++) {
        int col = warp_n * 48 + j * 8 + qpair * 2;
        __half* op0 = O + (size_t)(b * NLl + r0) * HHD + h * HDd + col;
        __half* op1 = O + (size_t)(b * NLl + r1) * HHD + h * HDd + col;
        *(__half2*)op0 = __floats2half2_rn(oac[j][0] * inv0, oac[j][1] * inv0);
        *(__half2*)op1 = __floats2half2_rn(oac[j][2] * inv1, oac[j][3] * inv1);
    }
}

// ======================= final layer norm -> d_out ==========================
__global__ void final_ln_kernel(float* __restrict__ out,
                                const float* __restrict__ w,
                                const float* __restrict__ bia) {
    int row = blockIdx.x;
    const float* x = g_lat + (size_t)row * Dd;
    float s = 0.f, ss = 0.f;
    for (int c = threadIdx.x; c < Dd; c += blockDim.x) {
        float v = x[c]; s += v; ss += v * v;
    }
#pragma unroll
    for (int o = 16; o > 0; o >>= 1) {
        s  += __shfl_xor_sync(0xffffffffu, s, o);
        ss += __shfl_xor_sync(0xffffffffu, ss, o);
    }
    __shared__ float red_s[8], red_q[8];
    __shared__ float sh_m, sh_r;
    int wrp = threadIdx.x >> 5, nl = threadIdx.x & 31;
    if (nl == 0) { red_s[wrp] = s; red_q[wrp] = ss; }
    __syncthreads();
    if (threadIdx.x == 0) {
        float S = 0.f, Q = 0.f;
        for (int i = 0; i < 8; i++) { S += red_s[i]; Q += red_q[i]; }
        float m = S / (float)Dd;
        sh_m = m;
        sh_r = rsqrtf(Q / (float)Dd - m * m + EPSf);
    }
    __syncthreads();
    float m = sh_m, r = sh_r;
    for (int c = threadIdx.x; c < Dd; c += blockDim.x)
        out[(size_t)row * Dd + c] = (x[c] - m) * r * w[c] + bia[c];
}

// ======================= launch (dual-stream, record-before-wait) ===========
extern "C" void kernel_launch(void* const* d_in, const int* in_sizes, int n_in,
                              void* d_out, int out_size) {
    const float* context  = (const float*)d_in[0];
    const float* latents  = (const float*)d_in[1];
    const float* ctx_ln_w = (const float*)d_in[2];
    const float* ctx_ln_b = (const float*)d_in[3];
    const float* lat_ln_w = (const float*)d_in[4];
    const float* lat_ln_b = (const float*)d_in[5];
    const float* q_ln_w   = (const float*)d_in[6];
    const float* q_ln_b   = (const float*)d_in[7];
    const float* k_ln_w   = (const float*)d_in[8];
    const float* k_ln_b   = (const float*)d_in[9];
    const float* wq       = (const float*)d_in[10];
    const float* wk       = (const float*)d_in[11];
    const float* wv       = (const float*)d_in[12];
    const float* wo       = (const float*)d_in[13];
    const float* mlp_ln_w = (const float*)d_in[14];
    const float* mlp_ln_b = (const float*)d_in[15];
    const float* w_fc     = (const float*)d_in[16];
    const float* w_cproj  = (const float*)d_in[17];
    const float* fin_w    = (const float*)d_in[18];
    const float* fin_b    = (const float*)d_in[19];
    (void)in_sizes; (void)n_in; (void)out_size;

    float *pLat, *pBias;
    __half *pW, *pActx, *pAlat, *pAmlp, *pQh, *pK0, *pV0, *pK1, *pV1, *pAttnH;
    cudaGetSymbolAddress((void**)&pLat,   g_lat);
    cudaGetSymbolAddress((void**)&pBias,  g_bias);
    cudaGetSymbolAddress((void**)&pW,     g_W);
    cudaGetSymbolAddress((void**)&pActx,  g_Actx);
    cudaGetSymbolAddress((void**)&pAlat,  g_Alat);
    cudaGetSymbolAddress((void**)&pAmlp,  g_Amlp);
    cudaGetSymbolAddress((void**)&pQh,    g_Qh);
    cudaGetSymbolAddress((void**)&pK0,    g_K0);
    cudaGetSymbolAddress((void**)&pV0,    g_V0);
    cudaGetSymbolAddress((void**)&pK1,    g_K1);
    cudaGetSymbolAddress((void**)&pV1,    g_V1);
    cudaGetSymbolAddress((void**)&pAttnH, g_attnH);
    __half* Kb[2] = {pK0, pK1};
    __half* Vb[2] = {pV0, pV1};

    cudaFuncSetAttribute(attention_kernel,
                         cudaFuncAttributeMaxDynamicSharedMemorySize, ATT_SMEM);
    cudaFuncSetAttribute(gemm_h_kernel<__half>,
                         cudaFuncAttributeMaxDynamicSharedMemorySize, GSMEM);
    cudaFuncSetAttribute(gemm_h_kernel<float>,
                         cudaFuncAttributeMaxDynamicSharedMemorySize, GSMEM);

    cudaStream_t sS;
    cudaStreamCreateWithFlags(&sS, cudaStreamNonBlocking);
    cudaEvent_t evFork, evCtx[DEPTHn], evAttn0;
    cudaEventCreateWithFlags(&evFork, cudaEventDisableTiming);
    cudaEventCreateWithFlags(&evAttn0, cudaEventDisableTiming);
    for (int i = 0; i < DEPTHn; i++)
        cudaEventCreateWithFlags(&evCtx[i], cudaEventDisableTiming);

    const int ML = Bb * NLl;   // 2048
    const int MC = Bb * Ss;    // 65536
    dim3 tb(32, 8);

    auto issue_ctx = [&](int i, int buf) {
        size_t wb = (size_t)i * LAYER_W;
        const float* gci = ctx_ln_w + i * Dd;
        const float* bci = ctx_ln_b + i * Dd;
        wt_packh_kernel<<<dim3(HHD / 32, Dd / 32), tb, 0, sS>>>(
            wk + (size_t)i * Dd * HHD, gci, pW + wb + OFF_WKF, Dd, HHD);
        bias_kernel<<<HHD / 16, 256, 0, sS>>>(
            bci, wk + (size_t)i * Dd * HHD, pBias + (i * 2 + 0) * HHD, Dd, HHD);
        wt_packh_kernel<<<dim3(HHD / 32, Dd / 32), tb, 0, sS>>>(
            wv + (size_t)i * Dd * HHD, gci, pW + wb + OFF_WVF, Dd, HHD);
        bias_kernel<<<HHD / 16, 256, 0, sS>>>(
            bci, wv + (size_t)i * Dd * HHD, pBias + (i * 2 + 1) * HHD, Dd, HHD);
        gemm_h_kernel<__half><<<dim3(2 * HHD / 128, MC / 128), 128, GSMEM, sS>>>(
            pActx, pW + wb + OFF_WKF, nullptr, Kb[buf], Vb[buf], 2,
            Dd, 2 * HHD, HHD, pBias + i * 2 * HHD, nullptr, 0, 2);
        cudaEventRecord(evCtx[i], sS);
    };

    packln_kernel<<<MC, 256>>>(context, nullptr, nullptr, pActx, Dd);
    cudaEventRecord(evFork, 0);
    cudaStreamWaitEvent(sS, evFork, 0);

    issue_ctx(0, 0);
    issue_ctx(1, 1);

    // latent-side weight packs (batched q/k/v; wo/fc/cproj separate)
    for (int i = 0; i < DEPTHn; i++) {
        size_t wb = (size_t)i * LAYER_W;
        wt_packh3_kernel<<<dim3(HHD / 32, Dd / 32, 3), tb>>>(
            wq + (size_t)i * Dd * HHD, wk + (size_t)i * Dd * HHD,
            wv + (size_t)i * Dd * HHD,
            pW + wb + OFF_WQ, pW + wb + OFF_WK, pW + wb + OFF_WV, Dd, HHD);
        wt_packh_kernel<<<dim3(Dd / 32, HHD / 32), tb>>>(
            wo + (size_t)i * HHD * Dd, nullptr, pW + wb + OFF_WO, HHD, Dd);
        wt_packh_kernel<<<dim3(FFf / 32, Dd / 32), tb>>>(
            w_fc + (size_t)i * Dd * FFf, nullptr, pW + wb + OFF_WFC, Dd, FFf);
        wt_packh_kernel<<<dim3(Dd / 32, FFf / 32), tb>>>(
            w_cproj + (size_t)i * FFf * Dd, nullptr, pW + wb + OFF_WCP, FFf, Dd);
    }
    broadcast_lat_kernel<<<(Bb * NLl * Dd + 255) / 256, 256>>>(latents);

    for (int i = 0; i < DEPTHn; i++) {
        size_t wb = (size_t)i * LAYER_W;
        const float* llw = lat_ln_w + i * Dd, *llb = lat_ln_b + i * Dd;
        const float* mlw = mlp_ln_w + i * Dd, *mlb = mlp_ln_b + i * Dd;
        const float* qlw = q_ln_w + i * HDd, *qlb = q_ln_b + i * HDd;
        const float* klw = k_ln_w + i * HDd, *klb = k_ln_b + i * HDd;
        int buf = i & 1;

        packln_kernel<<<ML, 256>>>(pLat, llw, llb, pAlat, Dd);
        gemm_h_kernel<__half><<<dim3(3 * HHD / 128, ML / 128), 128, GSMEM>>>(
            pAlat, pW + wb + OFF_WQ, pQh, Kb[buf], Vb[buf], 3,
            Dd, 3 * HHD, HHD, nullptr, nullptr, 0, 0);

        cudaStreamWaitEvent(0, evCtx[i], 0);
        attention_kernel<<<Bb * Hh, 256, ATT_SMEM>>>(pQh, Kb[buf], Vb[buf],
                                                     pAttnH, qlw, qlb, klw, klb);
        if (i == 0) {
            cudaEventRecord(evAttn0, 0);
            cudaStreamWaitEvent(sS, evAttn0, 0);
            issue_ctx(2, 0);
        }

        gemm_h_kernel<float><<<dim3(Dd / 128, ML / 128), 128, GSMEM>>>(
            pAttnH, pW + wb + OFF_WO, pLat, nullptr, nullptr, 0,
            HHD, Dd, Dd, nullptr, pLat, 0, 0);

        packln_kernel<<<ML, 256>>>(pLat, mlw, mlb, pAlat, Dd);
        gemm_h_kernel<__half><<<dim3(FFf / 128, ML / 128), 128, GSMEM>>>(
            pAlat, pW + wb + OFF_WFC, pAmlp, nullptr, nullptr, 0,
            Dd, FFf, FFf, nullptr, nullptr, 1, 0);
        gemm_h_kernel<float><<<dim3(Dd / 128, ML / 128), 128, GSMEM>>>(
            pAmlp, pW + wb + OFF_WCP, pLat, nullptr, nullptr, 0,
            FFf, Dd, Dd, nullptr, pLat, 0, 0);
    }

    final_ln_kernel<<<Bb * NLl, 256>>>((float*)d_out, fin_w, fin_b);
}

// round 17
// speedup vs baseline: 1.0500x; 1.0120x over previous
#include <cuda_runtime.h>
#include <cuda_fp16.h>
#include <cstdint>
#include <math.h>

#define Bb     32
#define Ss     2048
#define Dd     1280
#define Hh     16
#define HDd    96
#define NLl    64
#define DEPTHn 3
#define FFf    5120
#define SKV    (Ss + NLl)      /* 2112 */
#define HHD    (Hh * HDd)      /* 1536 */
#define EPSf   1e-5f

// ======================= scratch (device globals) ===========================
__device__ float g_lat[Bb * NLl * Dd];
__device__ float g_bias[DEPTHn * 2 * HHD];
__device__ __half g_Qh[Bb * NLl * HHD];
__device__ __half g_K0[(size_t)Bb * SKV * HHD];
__device__ __half g_V0[(size_t)Bb * SKV * HHD];
__device__ __half g_K1[(size_t)Bb * SKV * HHD];
__device__ __half g_V1[(size_t)Bb * SKV * HHD];
__device__ __half g_attnH[Bb * NLl * HHD];
__device__ __half g_Amlp[(size_t)Bb * NLl * FFf];

#define SZ1      1966080u
#define SZFC     6553600u
#define OFF_WQ   0u
#define OFF_WK   (SZ1)
#define OFF_WV   (2u * SZ1)
#define OFF_WKF  (3u * SZ1)
#define OFF_WVF  (4u * SZ1)
#define OFF_WO   (5u * SZ1)
#define OFF_WFC  (6u * SZ1)
#define OFF_WCP  (6u * SZ1 + SZFC)
#define LAYER_W  (6u * SZ1 + 2u * SZFC)
__device__ __half g_W[(size_t)DEPTHn * LAYER_W];
__device__ __half g_Actx[(size_t)Bb * Ss * Dd];
__device__ __half g_Alat[Bb * NLl * Dd];

// ======================= prep kernels ========================================
__global__ void packln_kernel(const float* __restrict__ X,
                              const float* __restrict__ lnw,
                              const float* __restrict__ lnb,
                              __half* __restrict__ out, int ncols) {
    int row = blockIdx.x;
    const float* x = X + (size_t)row * ncols;
    __half* o = out + (size_t)row * ncols;
    float v[8];
    int nv = 0;
    float s = 0.f, ss = 0.f;
    for (int c = threadIdx.x; c < ncols; c += blockDim.x) {
        float t = x[c];
        v[nv++] = t;
        s += t; ss += t * t;
    }
#pragma unroll
    for (int o2 = 16; o2 > 0; o2 >>= 1) {
        s  += __shfl_xor_sync(0xffffffffu, s, o2);
        ss += __shfl_xor_sync(0xffffffffu, ss, o2);
    }
    __shared__ float red_s[8], red_q[8];
    __shared__ float sh_m, sh_r;
    int w = threadIdx.x >> 5, nl = threadIdx.x & 31;
    if (nl == 0) { red_s[w] = s; red_q[w] = ss; }
    __syncthreads();
    if (threadIdx.x == 0) {
        float S = 0.f, Q = 0.f;
        int nw = blockDim.x >> 5;
        for (int i = 0; i < nw; i++) { S += red_s[i]; Q += red_q[i]; }
        float m = S / (float)ncols;
        sh_m = m;
        sh_r = rsqrtf(Q / (float)ncols - m * m + EPSf);
    }
    __syncthreads();
    float mu = sh_m, rs = sh_r;
    nv = 0;
    for (int c = threadIdx.x; c < ncols; c += blockDim.x) {
        float t = (v[nv++] - mu) * rs;
        if (lnw) t = t * lnw[c] + lnb[c];
        o[c] = __float2half_rn(t);
    }
}

__global__ void broadcast_lat_kernel(const float* __restrict__ latents) {
    int i = blockIdx.x * blockDim.x + threadIdx.x;
    const int per = NLl * Dd;
    if (i < Bb * per) g_lat[i] = latents[i % per];
}

__global__ void wt_packh_kernel(const float* __restrict__ W,
                                const float* __restrict__ gamma,
                                __half* __restrict__ out, int K, int N) {
    __shared__ float tile[32][33];
    int n0 = blockIdx.x << 5, k0 = blockIdx.y << 5;
    for (int i = threadIdx.y; i < 32; i += 8)
        tile[i][threadIdx.x] = W[(size_t)(k0 + i) * N + n0 + threadIdx.x];
    __syncthreads();
    float g = gamma ? gamma[k0 + threadIdx.x] : 1.f;
    for (int i = threadIdx.y; i < 32; i += 8)
        out[(size_t)(n0 + i) * K + k0 + threadIdx.x] =
            __float2half_rn(tile[threadIdx.x][i] * g);
}

// batched transpose-pack: z selects among 3 (W, out) pairs, no gamma
__global__ void wt_packh3_kernel(const float* __restrict__ W0,
                                 const float* __restrict__ W1,
                                 const float* __restrict__ W2,
                                 __half* __restrict__ o0,
                                 __half* __restrict__ o1,
                                 __half* __restrict__ o2, int K, int N) {
    const float* W = (blockIdx.z == 0) ? W0 : (blockIdx.z == 1 ? W1 : W2);
    __half* out    = (blockIdx.z == 0) ? o0 : (blockIdx.z == 1 ? o1 : o2);
    __shared__ float tile[32][33];
    int n0 = blockIdx.x << 5, k0 = blockIdx.y << 5;
    for (int i = threadIdx.y; i < 32; i += 8)
        tile[i][threadIdx.x] = W[(size_t)(k0 + i) * N + n0 + threadIdx.x];
    __syncthreads();
    for (int i = threadIdx.y; i < 32; i += 8)
        out[(size_t)(n0 + i) * K + k0 + threadIdx.x] =
            __float2half_rn(tile[threadIdx.x][i]);
}

__global__ void bias_kernel(const float* __restrict__ beta,
                            const float* __restrict__ W,
                            float* __restrict__ out, int K, int N) {
    __shared__ float red[16][17];
    int n = blockIdx.x * 16 + (threadIdx.x & 15);
    int kg = threadIdx.x >> 4;
    float s = 0.f;
    for (int k = kg; k < K; k += 16) s += beta[k] * W[(size_t)k * N + n];
    red[kg][threadIdx.x & 15] = s;
    __syncthreads();
    if (kg == 0) {
        float t = 0.f;
#pragma unroll
        for (int i = 0; i < 16; i++) t += red[i][threadIdx.x & 15];
        out[n] = t;
    }
}

// ===== fp16 HMMA GEMM: CTA 128xBN, 4 warps, BN=128 (2/SM) | BN=64 (3/SM) ===
#define CP_ASYNC16(dst, src) \
    asm volatile("cp.async.cg.shared.global [%0], [%1], 16;" \
                 :: "r"(dst), "l"(src))
#define CP_COMMIT() asm volatile("cp.async.commit_group;" ::: "memory")
#define CP_WAITG(n) asm volatile("cp.async.wait_group %0;" :: "n"(n) : "memory")

#define LDSM4(r0, r1, r2, r3, addr)                                          \
    asm volatile("ldmatrix.sync.aligned.m8n8.x4.shared.b16 {%0,%1,%2,%3}, [%4];" \
        : "=r"(r0), "=r"(r1), "=r"(r2), "=r"(r3) : "r"(addr))

#define LDSM4T(r0, r1, r2, r3, addr)                                         \
    asm volatile("ldmatrix.sync.aligned.m8n8.x4.trans.shared.b16 {%0,%1,%2,%3}, [%4];" \
        : "=r"(r0), "=r"(r1), "=r"(r2), "=r"(r3) : "r"(addr))

#define MMAH(d, a, b0, b1)                                                   \
    asm volatile("mma.sync.aligned.m16n8k16.row.col.f32.f16.f16.f32 "        \
        "{%0,%1,%2,%3}, {%4,%5,%6,%7}, {%8,%9}, {%0,%1,%2,%3};"              \
        : "+f"((d)[0]), "+f"((d)[1]), "+f"((d)[2]), "+f"((d)[3])             \
        : "r"((a)[0]), "r"((a)[1]), "r"((a)[2]), "r"((a)[3]),                \
          "r"(b0), "r"(b1))

__device__ __forceinline__ uint32_t smem_u32(const void* p) {
    uint32_t a;
    asm("{ .reg .u64 t; cvta.to.shared.u64 t, %1; cvt.u32.u64 %0, t; }"
        : "=r"(a) : "l"(p));
    return a;
}
__device__ __forceinline__ uint32_t swz(uint32_t off) {
    return off ^ ((off >> 3) & 0x70);
}
__device__ __forceinline__ void store2(float* p, float a, float b) {
    *(float2*)p = make_float2(a, b);
}
__device__ __forceinline__ void store2(__half* p, float a, float b) {
    *(__half2*)p = __floats2half2_rn(a, b);
}

#define SMEMB(BN) (3 * (16384 + (BN) * 128))

// split: 0 = single output Cq | 2 = ctx K|V | 3 = latent Q|K|V
template <int BN, typename OutT>
__global__ __launch_bounds__(128, BN == 128 ? 2 : 3) void gemm_h_kernel(
    const __half* __restrict__ Ain, const __half* __restrict__ Win,
    OutT* __restrict__ Cq, OutT* __restrict__ Ck, OutT* __restrict__ Cv,
    int split, int K, int N, int ldc,
    const float* __restrict__ bias, const float* __restrict__ resid,
    int relu, int remap) {
    constexpr int WN = BN / 2;           // per-warp n extent
    constexpr int NT = WN / 8;           // 8 or 4
    constexpr int ABYTES = 16384;
    constexpr int ST = ABYTES + BN * 128;
    constexpr int IB = BN / 16;          // B copy iters (8 or 4)
    extern __shared__ char sm[];
    uint32_t smb = smem_u32(sm);
    int tid = threadIdx.x, wid = tid >> 5, lane = tid & 31;
    int warp_m = wid >> 1, warp_n = wid & 1;

    int m0 = blockIdx.y << 7, n0 = blockIdx.x * BN;
    int NC = K >> 6;

    int rowb = tid >> 3, c16 = tid & 7;
    uint32_t sOf0 = swz((uint32_t)(rowb * 128 + c16 * 16));
    const __half* gA0 = Ain + (size_t)(m0 + rowb) * K + c16 * 8;
    const __half* gB0 = Win + (size_t)(n0 + rowb) * K + c16 * 8;
    size_t K16 = (size_t)16 * K;

    int lrow = lane & 15, lhalf = lane >> 4;
    int r7 = lrow & 7;
    uint32_t xk[4];
#pragma unroll
    for (int kq = 0; kq < 4; kq++)
        xk[kq] = (uint32_t)(((kq * 2 + lhalf) ^ r7) << 4);
    uint32_t aBase = (uint32_t)((warp_m * 64 + lrow) * 128);
    uint32_t bBase = (uint32_t)ABYTES + (uint32_t)((warp_n * WN + lrow) * 128);

    float acc[4][NT][4];
#pragma unroll
    for (int i = 0; i < 4; i++)
#pragma unroll
        for (int j = 0; j < NT; j++)
#pragma unroll
            for (int k = 0; k < 4; k++) acc[i][j][k] = 0.f;

    auto issue = [&](uint32_t stb, int c) {
        int koff = c * 64;
        const __half* a = gA0 + koff;
        uint32_t so = sOf0;
#pragma unroll
        for (int i = 0; i < 8; i++) {
            CP_ASYNC16(stb + so, a);
            so += 2048u; a += K16;
        }
        const __half* b = gB0 + koff;
        so = sOf0;
#pragma unroll
        for (int i = 0; i < IB; i++) {
            CP_ASYNC16(stb + (uint32_t)ABYTES + so, b);
            so += 2048u; b += K16;
        }
        CP_COMMIT();
    };

    issue(smb, 0);
    issue(smb + (uint32_t)ST, 1);

    for (int c = 0; c < NC; c++) {
        if (c + 1 < NC) { CP_WAITG(1); } else { CP_WAITG(0); }
        __syncthreads();
        uint32_t st = smb + (uint32_t)((c % 3) * ST);
#pragma unroll
        for (int kq = 0; kq < 4; kq++) {
            uint32_t ah[4][4];
#pragma unroll
            for (int mt = 0; mt < 4; mt++)
                LDSM4(ah[mt][0], ah[mt][1], ah[mt][2], ah[mt][3],
                      st + aBase + (uint32_t)(mt * 2048) + xk[kq]);
#pragma unroll
            for (int nt2 = 0; nt2 < NT / 2; nt2++) {
                uint32_t r0, r1, r2, r3;
                LDSM4(r0, r1, r2, r3,
                      st + bBase + (uint32_t)(nt2 * 2048) + xk[kq]);
#pragma unroll
                for (int mt = 0; mt < 4; mt++) {
                    MMAH(acc[mt][nt2 * 2],     ah[mt], r0, r2);
                    MMAH(acc[mt][nt2 * 2 + 1], ah[mt], r1, r3);
                }
            }
        }
        if (c + 2 < NC)
            issue(smb + (uint32_t)(((c + 2) % 3) * ST), c + 2);
    }

    // epilogue: destination by column segment (CTA lies in one segment)
    OutT* Cd = Cq;
    int rm = remap;
    int nloc = n0;
    if (split) {
        int seg = n0 / HHD;
        nloc = n0 - seg * HHD;
        if (split == 2) { Cd = seg ? Cv : Ck; rm = 2; }
        else { Cd = (seg == 0) ? Cq : (seg == 1 ? Ck : Cv); rm = (seg == 0) ? 0 : 1; }
    }
    int qrow = lane >> 2, qcol = (lane & 3) * 2;
#pragma unroll
    for (int mt = 0; mt < 4; mt++) {
#pragma unroll
        for (int half = 0; half < 2; half++) {
            int r = m0 + warp_m * 64 + mt * 16 + half * 8 + qrow;
            int crow;
            if (rm == 1)      crow = (r >> 6)  * SKV + Ss + (r & 63);
            else if (rm == 2) crow = (r >> 11) * SKV + (r & 2047);
            else              crow = r;
            OutT* cp = Cd + (size_t)crow * ldc + nloc + warp_n * WN;
            const float* rp = resid ? resid + (size_t)r * N + n0 + warp_n * WN
                                    : nullptr;
            const float* bp = bias ? bias + n0 + warp_n * WN : nullptr;
#pragma unroll
            for (int nt = 0; nt < NT; nt++) {
                float v0 = acc[mt][nt][half * 2];
                float v1 = acc[mt][nt][half * 2 + 1];
                int col = nt * 8 + qcol;
                if (bp) { v0 += bp[col]; v1 += bp[col + 1]; }
                if (rp) { v0 += rp[col]; v1 += rp[col + 1]; }
                if (relu) { v0 = fmaxf(v0, 0.f); v1 = fmaxf(v1, 0.f); }
                store2(cp + col, v0, v1);
            }
        }
    }
}

// ======================= HMMA flash attention ===============================
#define AQS   0
#define AKS   13312
#define AVS   26624
#define APS   39936
#define AMB   49152
#define ALR   49664
#define AMX   49920
#define ASM_  50432
#define ATT_SMEM 50944

__global__ __launch_bounds__(256) void attention_kernel(
    const __half* __restrict__ Q, const __half* __restrict__ Kb,
    const __half* __restrict__ Vb, __half* __restrict__ O,
    const float* __restrict__ qw, const float* __restrict__ qb,
    const float* __restrict__ kw, const float* __restrict__ kb) {
    extern __shared__ char smc[];
    __half* qs = (__half*)(smc + AQS);
    __half* ks = (__half*)(smc + AKS);
    __half* vs = (__half*)(smc + AVS);
    __half* psm = (__half*)(smc + APS);
    float* mbuf = (float*)(smc + AMB);
    float* lrun = (float*)(smc + ALR);
    float* rmx  = (float*)(smc + AMX);
    float* rsm  = (float*)(smc + ASM_);
    uint32_t smb = smem_u32(smc);

    int tid = threadIdx.x, wid = tid >> 5, lane = tid & 31;
    int warp_m = wid >> 1, warp_n = wid & 1;
    int b = blockIdx.x >> 4, h = blockIdx.x & 15;
    const float qscale = rsqrtf((float)HDd);

    int jrow = tid >> 2, part = tid & 3;
    int lrow = lane & 15, lhalf = lane >> 4;
    int qrow = lane >> 2, qpair = lane & 3;
    int r0 = warp_m * 16 + qrow, r1 = r0 + 8;

    {
        const __half* qp = Q + (size_t)(b * NLl + jrow) * HHD + h * HDd + part * 24;
        float v[24];
        float s = 0.f, ss = 0.f;
#pragma unroll
        for (int i = 0; i < 3; i++) {
            uint4 t = *(const uint4*)(qp + i * 8);
            __half2* hp = (__half2*)&t;
#pragma unroll
            for (int j = 0; j < 4; j++) {
                float2 f = __half22float2(hp[j]);
                v[i * 8 + 2 * j] = f.x; v[i * 8 + 2 * j + 1] = f.y;
            }
        }
#pragma unroll
        for (int i = 0; i < 24; i++) { s += v[i]; ss += v[i] * v[i]; }
#pragma unroll
        for (int o = 1; o < 4; o <<= 1) {
            s  += __shfl_xor_sync(0xffffffffu, s, o);
            ss += __shfl_xor_sync(0xffffffffu, ss, o);
        }
        float mmu = s * (1.f / 96.f);
        float rsd = rsqrtf(ss * (1.f / 96.f) - mmu * mmu + EPSf);
        __half2 hq[12];
#pragma unroll
        for (int i = 0; i < 12; i++) {
            int c = part * 24 + 2 * i;
            hq[i] = __floats2half2_rn(
                ((v[2 * i]     - mmu) * rsd * qw[c]     + qb[c])     * qscale,
                ((v[2 * i + 1] - mmu) * rsd * qw[c + 1] + qb[c + 1]) * qscale);
        }
        __half* dst = qs + jrow * 104 + part * 24;
        *(uint4*)(dst)      = *(uint4*)&hq[0];
        *(uint4*)(dst + 8)  = *(uint4*)&hq[4];
        *(uint4*)(dst + 16) = *(uint4*)&hq[8];
    }
    if (tid < 64) { mbuf[tid] = -1e30f; lrun[tid] = 0.f; }
    __syncthreads();

    float oac[6][4];
#pragma unroll
    for (int j = 0; j < 6; j++)
#pragma unroll
        for (int k = 0; k < 4; k++) oac[j][k] = 0.f;

    for (int t = 0; t < SKV / 64; t++) {
        {
            int kidx = t * 64 + jrow;
            const __half* kp = Kb + ((size_t)b * SKV + kidx) * HHD + h * HDd + part * 24;
            const __half* vp = Vb + ((size_t)b * SKV + kidx) * HHD + h * HDd + part * 24;
            uint4 kr[3], vr[3];
#pragma unroll
            for (int i = 0; i < 3; i++) {
                kr[i] = *(const uint4*)(kp + i * 8);
                vr[i] = *(const uint4*)(vp + i * 8);
            }
            float kv[24];
#pragma unroll
            for (int i = 0; i < 3; i++) {
                __half2* hk = (__half2*)&kr[i];
#pragma unroll
                for (int j = 0; j < 4; j++) {
                    float2 f = __half22float2(hk[j]);
                    kv[i * 8 + 2 * j] = f.x; kv[i * 8 + 2 * j + 1] = f.y;
                }
            }
            float s = 0.f, ss = 0.f;
#pragma unroll
            for (int i = 0; i < 24; i++) { s += kv[i]; ss += kv[i] * kv[i]; }
#pragma unroll
            for (int o = 1; o < 4; o <<= 1) {
                s  += __shfl_xor_sync(0xffffffffu, s, o);
                ss += __shfl_xor_sync(0xffffffffu, ss, o);
            }
            float mmu = s * (1.f / 96.f);
            float rsd = rsqrtf(ss * (1.f / 96.f) - mmu * mmu + EPSf);
            __half2 hk2[12];
#pragma unroll
            for (int i = 0; i < 12; i++) {
                int c = part * 24 + 2 * i;
                hk2[i] = __floats2half2_rn(
                    (kv[2 * i]     - mmu) * rsd * kw[c]     + kb[c],
                    (kv[2 * i + 1] - mmu) * rsd * kw[c + 1] + kb[c + 1]);
            }
            __half* kd = ks + jrow * 104 + part * 24;
            __half* vd = vs + jrow * 104 + part * 24;
            *(uint4*)(kd)      = *(uint4*)&hk2[0];
            *(uint4*)(kd + 8)  = *(uint4*)&hk2[4];
            *(uint4*)(kd + 16) = *(uint4*)&hk2[8];
            *(uint4*)(vd)      = vr[0];
            *(uint4*)(vd + 8)  = vr[1];
            *(uint4*)(vd + 16) = vr[2];
        }
        __syncthreads();

        float sc[4][4];
#pragma unroll
        for (int i = 0; i < 4; i++)
#pragma unroll
            for (int k = 0; k < 4; k++) sc[i][k] = 0.f;
#pragma unroll
        for (int k6 = 0; k6 < 6; k6++) {
            uint32_t a[4];
            LDSM4(a[0], a[1], a[2], a[3],
                  smb + AQS + (uint32_t)((warp_m * 16 + lrow) * 208 + (k6 * 2 + lhalf) * 16));
#pragma unroll
            for (int nt2 = 0; nt2 < 2; nt2++) {
                uint32_t b0, b1, b2, b3;
                LDSM4(b0, b1, b2, b3,
                      smb + AKS + (uint32_t)((warp_n * 32 + nt2 * 16 + lrow) * 208 +
                                             (k6 * 2 + lhalf) * 16));
                MMAH(sc[nt2 * 2],     a, b0, b2);
                MMAH(sc[nt2 * 2 + 1], a, b1, b3);
            }
        }

        float mx0 = -1e30f, mx1 = -1e30f;
#pragma unroll
        for (int nt = 0; nt < 4; nt++) {
            mx0 = fmaxf(mx0, fmaxf(sc[nt][0], sc[nt][1]));
            mx1 = fmaxf(mx1, fmaxf(sc[nt][2], sc[nt][3]));
        }
        mx0 = fmaxf(mx0, __shfl_xor_sync(0xffffffffu, mx0, 1));
        mx0 = fmaxf(mx0, __shfl_xor_sync(0xffffffffu, mx0, 2));
        mx1 = fmaxf(mx1, __shfl_xor_sync(0xffffffffu, mx1, 1));
        mx1 = fmaxf(mx1, __shfl_xor_sync(0xffffffffu, mx1, 2));
        if (qpair == 0) {
            rmx[r0 * 2 + warp_n] = mx0;
            rmx[r1 * 2 + warp_n] = mx1;
        }
        __syncthreads();

        int p = t & 1;
        float mo0 = mbuf[p * 64 + r0], mo1 = mbuf[p * 64 + r1];
        float mn0 = fmaxf(mo0, fmaxf(rmx[r0 * 2], rmx[r0 * 2 + 1]));
        float mn1 = fmaxf(mo1, fmaxf(rmx[r1 * 2], rmx[r1 * 2 + 1]));
        float cr0 = __expf(mo0 - mn0), cr1 = __expf(mo1 - mn1);
        if (warp_n == 0 && qpair == 0) {
            mbuf[(p ^ 1) * 64 + r0] = mn0;
            mbuf[(p ^ 1) * 64 + r1] = mn1;
        }
        float s0 = 0.f, s1 = 0.f;
#pragma unroll
        for (int nt = 0; nt < 4; nt++) {
            float e0 = __expf(sc[nt][0] - mn0);
            float e1 = __expf(sc[nt][1] - mn0);
            float e2 = __expf(sc[nt][2] - mn1);
            float e3 = __expf(sc[nt][3] - mn1);
            s0 += e0 + e1; s1 += e2 + e3;
            int col = warp_n * 32 + nt * 8 + qpair * 2;
            *(__half2*)(psm + r0 * 72 + col) = __floats2half2_rn(e0, e1);
            *(__half2*)(psm + r1 * 72 + col) = __floats2half2_rn(e2, e3);
        }
        s0 += __shfl_xor_sync(0xffffffffu, s0, 1);
        s0 += __shfl_xor_sync(0xffffffffu, s0, 2);
        s1 += __shfl_xor_sync(0xffffffffu, s1, 1);
        s1 += __shfl_xor_sync(0xffffffffu, s1, 2);
        if (qpair == 0) {
            rsm[r0 * 2 + warp_n] = s0;
            rsm[r1 * 2 + warp_n] = s1;
        }
        __syncthreads();
        if (warp_n == 0 && qpair == 0) {
            lrun[r0] = lrun[r0] * cr0 + rsm[r0 * 2] + rsm[r0 * 2 + 1];
            lrun[r1] = lrun[r1] * cr1 + rsm[r1 * 2] + rsm[r1 * 2 + 1];
        }

#pragma unroll
        for (int j = 0; j < 6; j++) {
            oac[j][0] *= cr0; oac[j][1] *= cr0;
            oac[j][2] *= cr1; oac[j][3] *= cr1;
        }
        int w8 = lane & 7, blk = lane >> 3;
#pragma unroll
        for (int kk = 0; kk < 4; kk++) {
            uint32_t a[4];
            LDSM4(a[0], a[1], a[2], a[3],
                  smb + APS + (uint32_t)((warp_m * 16 + lrow) * 144 + (kk * 2 + lhalf) * 16));
#pragma unroll
            for (int pr = 0; pr < 3; pr++) {
                int vrow = kk * 16 + w8 + 8 * (blk & 1);
                int vcol = warp_n * 48 + pr * 16 + 8 * (blk >> 1);
                uint32_t b0, b1, b2, b3;
                LDSM4T(b0, b1, b2, b3,
                       smb + AVS + (uint32_t)(vrow * 208 + vcol * 2));
                MMAH(oac[pr * 2],     a, b0, b1);
                MMAH(oac[pr * 2 + 1], a, b2, b3);
            }
        }
        __syncthreads();
    }

    float inv0 = 1.f / lrun[r0], inv1 = 1.f / lrun[r1];
#pragma unroll
    for (int j = 0; j < 6; j++) {
        int col = warp_n * 48 + j * 8 + qpair * 2;
        __half* op0 = O + (size_t)(b * NLl + r0) * HHD + h * HDd + col;
        __half* op1 = O + (size_t)(b * NLl + r1) * HHD + h * HDd + col;
        *(__half2*)op0 = __floats2half2_rn(oac[j][0] * inv0, oac[j][1] * inv0);
        *(__half2*)op1 = __floats2half2_rn(oac[j][2] * inv1, oac[j][3] * inv1);
    }
}

// ======================= final layer norm -> d_out ==========================
__global__ void final_ln_kernel(float* __restrict__ out,
                                const float* __restrict__ w,
                                const float* __restrict__ bia) {
    int row = blockIdx.x;
    const float* x = g_lat + (size_t)row * Dd;
    float s = 0.f, ss = 0.f;
    for (int c = threadIdx.x; c < Dd; c += blockDim.x) {
        float v = x[c]; s += v; ss += v * v;
    }
#pragma unroll
    for (int o = 16; o > 0; o >>= 1) {
        s  += __shfl_xor_sync(0xffffffffu, s, o);
        ss += __shfl_xor_sync(0xffffffffu, ss, o);
    }
    __shared__ float red_s[8], red_q[8];
    __shared__ float sh_m, sh_r;
    int wrp = threadIdx.x >> 5, nl = threadIdx.x & 31;
    if (nl == 0) { red_s[wrp] = s; red_q[wrp] = ss; }
    __syncthreads();
    if (threadIdx.x == 0) {
        float S = 0.f, Q = 0.f;
        for (int i = 0; i < 8; i++) { S += red_s[i]; Q += red_q[i]; }
        float m = S / (float)Dd;
        sh_m = m;
        sh_r = rsqrtf(Q / (float)Dd - m * m + EPSf);
    }
    __syncthreads();
    float m = sh_m, r = sh_r;
    for (int c = threadIdx.x; c < Dd; c += blockDim.x)
        out[(size_t)row * Dd + c] = (x[c] - m) * r * w[c] + bia[c];
}

// ======================= launch (dual-stream, record-before-wait) ===========
extern "C" void kernel_launch(void* const* d_in, const int* in_sizes, int n_in,
                              void* d_out, int out_size) {
    const float* context  = (const float*)d_in[0];
    const float* latents  = (const float*)d_in[1];
    const float* ctx_ln_w = (const float*)d_in[2];
    const float* ctx_ln_b = (const float*)d_in[3];
    const float* lat_ln_w = (const float*)d_in[4];
    const float* lat_ln_b = (const float*)d_in[5];
    const float* q_ln_w   = (const float*)d_in[6];
    const float* q_ln_b   = (const float*)d_in[7];
    const float* k_ln_w   = (const float*)d_in[8];
    const float* k_ln_b   = (const float*)d_in[9];
    const float* wq       = (const float*)d_in[10];
    const float* wk       = (const float*)d_in[11];
    const float* wv       = (const float*)d_in[12];
    const float* wo       = (const float*)d_in[13];
    const float* mlp_ln_w = (const float*)d_in[14];
    const float* mlp_ln_b = (const float*)d_in[15];
    const float* w_fc     = (const float*)d_in[16];
    const float* w_cproj  = (const float*)d_in[17];
    const float* fin_w    = (const float*)d_in[18];
    const float* fin_b    = (const float*)d_in[19];
    (void)in_sizes; (void)n_in; (void)out_size;

    float *pLat, *pBias;
    __half *pW, *pActx, *pAlat, *pAmlp, *pQh, *pK0, *pV0, *pK1, *pV1, *pAttnH;
    cudaGetSymbolAddress((void**)&pLat,   g_lat);
    cudaGetSymbolAddress((void**)&pBias,  g_bias);
    cudaGetSymbolAddress((void**)&pW,     g_W);
    cudaGetSymbolAddress((void**)&pActx,  g_Actx);
    cudaGetSymbolAddress((void**)&pAlat,  g_Alat);
    cudaGetSymbolAddress((void**)&pAmlp,  g_Amlp);
    cudaGetSymbolAddress((void**)&pQh,    g_Qh);
    cudaGetSymbolAddress((void**)&pK0,    g_K0);
    cudaGetSymbolAddress((void**)&pV0,    g_V0);
    cudaGetSymbolAddress((void**)&pK1,    g_K1);
    cudaGetSymbolAddress((void**)&pV1,    g_V1);
    cudaGetSymbolAddress((void**)&pAttnH, g_attnH);
    __half* Kb[2] = {pK0, pK1};
    __half* Vb[2] = {pV0, pV1};

    cudaFuncSetAttribute(attention_kernel,
                         cudaFuncAttributeMaxDynamicSharedMemorySize, ATT_SMEM);
    cudaFuncSetAttribute(gemm_h_kernel<128, __half>,
                         cudaFuncAttributeMaxDynamicSharedMemorySize, SMEMB(128));
    cudaFuncSetAttribute(gemm_h_kernel<128, float>,
                         cudaFuncAttributeMaxDynamicSharedMemorySize, SMEMB(128));
    cudaFuncSetAttribute(gemm_h_kernel<64, float>,
                         cudaFuncAttributeMaxDynamicSharedMemorySize, SMEMB(64));

    cudaStream_t sS;
    cudaStreamCreateWithFlags(&sS, cudaStreamNonBlocking);
    cudaEvent_t evFork, evCtx[DEPTHn], evAttn0;
    cudaEventCreateWithFlags(&evFork, cudaEventDisableTiming);
    cudaEventCreateWithFlags(&evAttn0, cudaEventDisableTiming);
    for (int i = 0; i < DEPTHn; i++)
        cudaEventCreateWithFlags(&evCtx[i], cudaEventDisableTiming);

    const int ML = Bb * NLl;   // 2048
    const int MC = Bb * Ss;    // 65536
    dim3 tb(32, 8);

    auto issue_ctx = [&](int i, int buf) {
        size_t wb = (size_t)i * LAYER_W;
        const float* gci = ctx_ln_w + i * Dd;
        const float* bci = ctx_ln_b + i * Dd;
        wt_packh_kernel<<<dim3(HHD / 32, Dd / 32), tb, 0, sS>>>(
            wk + (size_t)i * Dd * HHD, gci, pW + wb + OFF_WKF, Dd, HHD);
        bias_kernel<<<HHD / 16, 256, 0, sS>>>(
            bci, wk + (size_t)i * Dd * HHD, pBias + (i * 2 + 0) * HHD, Dd, HHD);
        wt_packh_kernel<<<dim3(HHD / 32, Dd / 32), tb, 0, sS>>>(
            wv + (size_t)i * Dd * HHD, gci, pW + wb + OFF_WVF, Dd, HHD);
        bias_kernel<<<HHD / 16, 256, 0, sS>>>(
            bci, wv + (size_t)i * Dd * HHD, pBias + (i * 2 + 1) * HHD, Dd, HHD);
        gemm_h_kernel<128, __half><<<dim3(2 * HHD / 128, MC / 128), 128,
                                     SMEMB(128), sS>>>(
            pActx, pW + wb + OFF_WKF, nullptr, Kb[buf], Vb[buf], 2,
            Dd, 2 * HHD, HHD, pBias + i * 2 * HHD, nullptr, 0, 2);
        cudaEventRecord(evCtx[i], sS);
    };

    packln_kernel<<<MC, 256>>>(context, nullptr, nullptr, pActx, Dd);
    cudaEventRecord(evFork, 0);
    cudaStreamWaitEvent(sS, evFork, 0);

    issue_ctx(0, 0);
    issue_ctx(1, 1);

    for (int i = 0; i < DEPTHn; i++) {
        size_t wb = (size_t)i * LAYER_W;
        wt_packh3_kernel<<<dim3(HHD / 32, Dd / 32, 3), tb>>>(
            wq + (size_t)i * Dd * HHD, wk + (size_t)i * Dd * HHD,
            wv + (size_t)i * Dd * HHD,
            pW + wb + OFF_WQ, pW + wb + OFF_WK, pW + wb + OFF_WV, Dd, HHD);
        wt_packh_kernel<<<dim3(Dd / 32, HHD / 32), tb>>>(
            wo + (size_t)i * HHD * Dd, nullptr, pW + wb + OFF_WO, HHD, Dd);
        wt_packh_kernel<<<dim3(FFf / 32, Dd / 32), tb>>>(
            w_fc + (size_t)i * Dd * FFf, nullptr, pW + wb + OFF_WFC, Dd, FFf);
        wt_packh_kernel<<<dim3(Dd / 32, FFf / 32), tb>>>(
            w_cproj + (size_t)i * FFf * Dd, nullptr, pW + wb + OFF_WCP, FFf, Dd);
    }
    broadcast_lat_kernel<<<(Bb * NLl * Dd + 255) / 256, 256>>>(latents);

    for (int i = 0; i < DEPTHn; i++) {
        size_t wb = (size_t)i * LAYER_W;
        const float* llw = lat_ln_w + i * Dd, *llb = lat_ln_b + i * Dd;
        const float* mlw = mlp_ln_w + i * Dd, *mlb = mlp_ln_b + i * Dd;
        const float* qlw = q_ln_w + i * HDd, *qlb = q_ln_b + i * HDd;
        const float* klw = k_ln_w + i * HDd, *klb = k_ln_b + i * HDd;
        int buf = i & 1;

        packln_kernel<<<ML, 256>>>(pLat, llw, llb, pAlat, Dd);
        gemm_h_kernel<128, __half><<<dim3(3 * HHD / 128, ML / 128), 128,
                                     SMEMB(128)>>>(
            pAlat, pW + wb + OFF_WQ, pQh, Kb[buf], Vb[buf], 3,
            Dd, 3 * HHD, HHD, nullptr, nullptr, 0, 0);

        cudaStreamWaitEvent(0, evCtx[i], 0);
        attention_kernel<<<Bb * Hh, 256, ATT_SMEM>>>(pQh, Kb[buf], Vb[buf],
                                                     pAttnH, qlw, qlb, klw, klb);
        if (i == 0) {
            cudaEventRecord(evAttn0, 0);
            cudaStreamWaitEvent(sS, evAttn0, 0);
            issue_ctx(2, 0);
        }

        // wo: BN=64 tiles (320 CTAs, 3 CTA/SM capacity)
        gemm_h_kernel<64, float><<<dim3(Dd / 64, ML / 128), 128, SMEMB(64)>>>(
            pAttnH, pW + wb + OFF_WO, pLat, nullptr, nullptr, 0,
            HHD, Dd, Dd, nullptr, pLat, 0, 0);

        packln_kernel<<<ML, 256>>>(pLat, mlw, mlb, pAlat, Dd);
        gemm_h_kernel<128, __half><<<dim3(FFf / 128, ML / 128), 128,
                                     SMEMB(128)>>>(
            pAlat, pW + wb + OFF_WFC, pAmlp, nullptr, nullptr, 0,
            Dd, FFf, FFf, nullptr, nullptr, 1, 0);
        // cproj: BN=64 tiles
        gemm_h_kernel<64, float><<<dim3(Dd / 64, ML / 128), 128, SMEMB(64)>>>(
            pAmlp, pW + wb + OFF_WCP, pLat, nullptr, nullptr, 0,
            FFf, Dd, Dd, nullptr, pLat, 0, 0);
    }

    final_ln_kernel<<<Bb * NLl, 256>>>((float*)d_out, fin_w, fin_b);
}